// round 2
// baseline (speedup 1.0000x reference)
#include <cuda_runtime.h>
#include <cuda_bf16.h>

// ---------------------------------------------------------------------------
// OACNNs block, fp32 baseline.
//   N=500000 points, C=64 channels, K=27 taps, 3 cluster scales.
// Pipeline (all launches on the default stream; graph-capturable):
//   per scale i:
//     P = feat @ W_lw[i]            (+ fused per-channel sum/sumsq for BN)
//     pw = relu(bn(P)); segsum(pw), cnt               (atomicAdd)
//     pw = (pw - mean[cl]) @ W_w[i]  (+ global atomicMax for softmax shift)
//     pw = exp(pw - max); segsum -> denom
//     Q = feat @ W_proj[i] (+stats); pf = relu(bn(Q)) * pw/(denom[cl]+1e-6)
//     segsum(pf) -> segA;  mix += adp[:,i] * segA[cl]
//   f_last = relu(bn(feat @ W_proj[3]))
//   fused  = relu(bn(f_last@Wf[0:64] + mix@Wf[64:128])) + feat
//   h  = relu(bn(conv27(fused, W1)));  h2 = bn(conv27(h, W2))
//   out = relu(h2 + fused)
// ---------------------------------------------------------------------------

#define NPTS_MAX 500000
#define NCL_MAX  131072

// scratch (device globals: allocation-free rule)
__device__ float    g_bufP[NPTS_MAX * 64];
__device__ float    g_bufQ[NPTS_MAX * 64];
__device__ float    g_bufM[NPTS_MAX * 64];
__device__ float    g_bufF[NPTS_MAX * 64];
__device__ float    g_adp [NPTS_MAX * 3];
__device__ float    g_segA[NCL_MAX * 64];
__device__ float    g_segB[NCL_MAX * 64];
__device__ float    g_cnt [NCL_MAX];
__device__ float    g_stats[128];   // [0:64) sum, [64:128) sumsq
__device__ float    g_coef [128];   // [0:64) scale a, [64:128) shift b
__device__ unsigned g_maxbits;

// ---------------- helpers ----------------
__device__ __forceinline__ unsigned fmax_map(float x) {
    unsigned b = __float_as_uint(x);
    return (b & 0x80000000u) ? ~b : (b | 0x80000000u);
}
__device__ __forceinline__ float fmax_unmap(unsigned u) {
    return (u & 0x80000000u) ? __uint_as_float(u & 0x7fffffffu)
                             : __uint_as_float(~u);
}

// 64x64 tile FFMA core: As is [64][65] (padded), Bs is [64][64].
// 64 threads; thread (tx=tid&7, ty=tid>>3) computes rows ty*8.. cols tx*8..
__device__ __forceinline__ void tile_mm(const float* __restrict__ As,
                                        const float* __restrict__ Bs,
                                        float acc[8][8], int tx, int ty) {
#pragma unroll 8
    for (int kk = 0; kk < 64; ++kk) {
        float a[8], b[8];
#pragma unroll
        for (int j = 0; j < 8; ++j) b[j] = Bs[kk * 64 + tx * 8 + j];
#pragma unroll
        for (int i = 0; i < 8; ++i) a[i] = As[(ty * 8 + i) * 65 + kk];
#pragma unroll
        for (int i = 0; i < 8; ++i)
#pragma unroll
            for (int j = 0; j < 8; ++j) acc[i][j] = fmaf(a[i], b[j], acc[i][j]);
    }
}

__device__ __forceinline__ void load_B64(float* Bs, const float* __restrict__ W,
                                         int tid) {
#pragma unroll
    for (int it = 0; it < 16; ++it)
        ((float4*)Bs)[tid + it * 64] = ((const float4*)W)[tid + it * 64];
}

// plain A tile load, zero-fill rows >= n
__device__ __forceinline__ void load_A64(float* As, const float* __restrict__ A,
                                         int row0, int n, int tid) {
    int c4 = (tid & 15) * 4;
    int rb = tid >> 4;
#pragma unroll
    for (int it = 0; it < 16; ++it) {
        int r = rb + it * 4;
        int row = row0 + r;
        float4 v = make_float4(0.f, 0.f, 0.f, 0.f);
        if (row < n) v = *(const float4*)(A + (size_t)row * 64 + c4);
        float* d = As + r * 65 + c4;
        d[0] = v.x; d[1] = v.y; d[2] = v.z; d[3] = v.w;
    }
}

// ---------------- GEMM: C = A@W, fused per-channel sum/sumsq ----------------
__global__ __launch_bounds__(64)
void k_gemm_stats(const float* __restrict__ A, const float* __restrict__ W,
                  float* __restrict__ Co, float* __restrict__ stats, int n) {
    __shared__ float As[64 * 65];
    __shared__ float Bs[64 * 64];
    __shared__ float csum[64], csq[64];
    int tid = threadIdx.x, tx = tid & 7, ty = tid >> 3;
    int row0 = blockIdx.x * 64;
    csum[tid] = 0.f; csq[tid] = 0.f;
    load_B64(Bs, W, tid);
    load_A64(As, A, row0, n, tid);
    __syncthreads();
    float acc[8][8] = {};
    tile_mm(As, Bs, acc, tx, ty);
#pragma unroll
    for (int i = 0; i < 8; ++i) {
        int row = row0 + ty * 8 + i;
        if (row < n) {
            *(float4*)(Co + (size_t)row * 64 + tx * 8) =
                make_float4(acc[i][0], acc[i][1], acc[i][2], acc[i][3]);
            *(float4*)(Co + (size_t)row * 64 + tx * 8 + 4) =
                make_float4(acc[i][4], acc[i][5], acc[i][6], acc[i][7]);
        }
    }
#pragma unroll
    for (int j = 0; j < 8; ++j) {
        float s = 0.f, q = 0.f;
#pragma unroll
        for (int i = 0; i < 8; ++i) { float v = acc[i][j]; s += v; q += v * v; }
        atomicAdd(&csum[tx * 8 + j], s);
        atomicAdd(&csq[tx * 8 + j], q);
    }
    __syncthreads();
    atomicAdd(&stats[tid], csum[tid]);
    atomicAdd(&stats[64 + tid], csq[tid]);
}

// ------- GEMM: C = (A - mean[cl])@W  (in-place ok), fused global max -------
__global__ __launch_bounds__(64)
void k_gemm_submean_max(const float* __restrict__ A, const float* __restrict__ W,
                        float* __restrict__ Co, const float* __restrict__ seg,
                        const float* __restrict__ cnt, const int* __restrict__ cl,
                        unsigned* __restrict__ gmax, int n) {
    __shared__ float As[64 * 65];
    __shared__ float Bs[64 * 64];
    __shared__ int   cls[64];
    __shared__ float cinv[64];
    __shared__ unsigned smax;
    int tid = threadIdx.x, tx = tid & 7, ty = tid >> 3;
    int row0 = blockIdx.x * 64;
    if (tid == 0) smax = 0u;
    {
        int row = row0 + tid;
        int c = (row < n) ? cl[row] : 0;
        cls[tid] = c;
        cinv[tid] = 1.f / fmaxf(cnt[c], 1.f);
    }
    load_B64(Bs, W, tid);
    __syncthreads();
    int c4 = (tid & 15) * 4;
    int rb = tid >> 4;
#pragma unroll
    for (int it = 0; it < 16; ++it) {
        int r = rb + it * 4;
        int row = row0 + r;
        float4 v = make_float4(0.f, 0.f, 0.f, 0.f);
        if (row < n) {
            v = *(const float4*)(A + (size_t)row * 64 + c4);
            const float* m = seg + (size_t)cls[r] * 64 + c4;
            float ci = cinv[r];
            v.x -= m[0] * ci; v.y -= m[1] * ci; v.z -= m[2] * ci; v.w -= m[3] * ci;
        }
        float* d = As + r * 65 + c4;
        d[0] = v.x; d[1] = v.y; d[2] = v.z; d[3] = v.w;
    }
    __syncthreads();
    float acc[8][8] = {};
    tile_mm(As, Bs, acc, tx, ty);
    unsigned lmax = 0u;
#pragma unroll
    for (int i = 0; i < 8; ++i) {
        int row = row0 + ty * 8 + i;
        if (row < n) {
            *(float4*)(Co + (size_t)row * 64 + tx * 8) =
                make_float4(acc[i][0], acc[i][1], acc[i][2], acc[i][3]);
            *(float4*)(Co + (size_t)row * 64 + tx * 8 + 4) =
                make_float4(acc[i][4], acc[i][5], acc[i][6], acc[i][7]);
#pragma unroll
            for (int j = 0; j < 8; ++j) lmax = max(lmax, fmax_map(acc[i][j]));
        }
    }
    atomicMax(&smax, lmax);
    __syncthreads();
    if (tid == 0) atomicMax(gmax, smax);
}

// -------- GEMM K=128: C = A1@W[0:64] + A2@W[64:128], fused stats --------
__global__ __launch_bounds__(64)
void k_gemm2_stats(const float* __restrict__ A1, const float* __restrict__ A2,
                   const float* __restrict__ W, float* __restrict__ Co,
                   float* __restrict__ stats, int n) {
    __shared__ float As[64 * 65];
    __shared__ float Bs[64 * 64];
    __shared__ float csum[64], csq[64];
    int tid = threadIdx.x, tx = tid & 7, ty = tid >> 3;
    int row0 = blockIdx.x * 64;
    csum[tid] = 0.f; csq[tid] = 0.f;
    float acc[8][8] = {};
#pragma unroll
    for (int p = 0; p < 2; ++p) {
        const float* Ap = p ? A2 : A1;
        __syncthreads();
        load_B64(Bs, W + p * 64 * 64, tid);
        load_A64(As, Ap, row0, n, tid);
        __syncthreads();
        tile_mm(As, Bs, acc, tx, ty);
    }
#pragma unroll
    for (int i = 0; i < 8; ++i) {
        int row = row0 + ty * 8 + i;
        if (row < n) {
            *(float4*)(Co + (size_t)row * 64 + tx * 8) =
                make_float4(acc[i][0], acc[i][1], acc[i][2], acc[i][3]);
            *(float4*)(Co + (size_t)row * 64 + tx * 8 + 4) =
                make_float4(acc[i][4], acc[i][5], acc[i][6], acc[i][7]);
        }
    }
#pragma unroll
    for (int j = 0; j < 8; ++j) {
        float s = 0.f, q = 0.f;
#pragma unroll
        for (int i = 0; i < 8; ++i) { float v = acc[i][j]; s += v; q += v * v; }
        atomicAdd(&csum[tx * 8 + j], s);
        atomicAdd(&csq[tx * 8 + j], q);
    }
    __syncthreads();
    atomicAdd(&stats[tid], csum[tid]);
    atomicAdd(&stats[64 + tid], csq[tid]);
}

// ------ gather conv: C = sum_k A[nbr[:,k]] @ Wc[k], fused stats ------
__global__ __launch_bounds__(64)
void k_conv_stats(const float* __restrict__ A, const int* __restrict__ nbr,
                  const float* __restrict__ Wc, float* __restrict__ Co,
                  float* __restrict__ stats, int n) {
    __shared__ float As[64 * 65];
    __shared__ float Bs[64 * 64];
    __shared__ float csum[64], csq[64];
    int tid = threadIdx.x, tx = tid & 7, ty = tid >> 3;
    int row0 = blockIdx.x * 64;
    csum[tid] = 0.f; csq[tid] = 0.f;
    float acc[8][8] = {};
    int c4 = (tid & 15) * 4;
    int rb = tid >> 4;
    for (int k = 0; k < 27; ++k) {
        __syncthreads();
        load_B64(Bs, Wc + k * 4096, tid);
#pragma unroll
        for (int it = 0; it < 16; ++it) {
            int r = rb + it * 4;
            int row = row0 + r;
            float4 v = make_float4(0.f, 0.f, 0.f, 0.f);
            if (row < n) {
                int src = nbr[(size_t)row * 27 + k];
                v = *(const float4*)(A + (size_t)src * 64 + c4);
            }
            float* d = As + r * 65 + c4;
            d[0] = v.x; d[1] = v.y; d[2] = v.z; d[3] = v.w;
        }
        __syncthreads();
        tile_mm(As, Bs, acc, tx, ty);
    }
#pragma unroll
    for (int i = 0; i < 8; ++i) {
        int row = row0 + ty * 8 + i;
        if (row < n) {
            *(float4*)(Co + (size_t)row * 64 + tx * 8) =
                make_float4(acc[i][0], acc[i][1], acc[i][2], acc[i][3]);
            *(float4*)(Co + (size_t)row * 64 + tx * 8 + 4) =
                make_float4(acc[i][4], acc[i][5], acc[i][6], acc[i][7]);
        }
    }
#pragma unroll
    for (int j = 0; j < 8; ++j) {
        float s = 0.f, q = 0.f;
#pragma unroll
        for (int i = 0; i < 8; ++i) { float v = acc[i][j]; s += v; q += v * v; }
        atomicAdd(&csum[tx * 8 + j], s);
        atomicAdd(&csq[tx * 8 + j], q);
    }
    __syncthreads();
    atomicAdd(&stats[tid], csum[tid]);
    atomicAdd(&stats[64 + tid], csq[tid]);
}

// ---------------- small / elementwise kernels ----------------
__global__ void k_bn_coef(const float* __restrict__ stats,
                          const float* __restrict__ g, const float* __restrict__ b,
                          float* __restrict__ coef, int n) {
    int c = threadIdx.x;
    if (c < 64) {
        float inv_n = 1.f / (float)n;
        float mean = stats[c] * inv_n;
        float var = stats[64 + c] * inv_n - mean * mean;
        float a = g[c] * rsqrtf(var + 1e-3f);
        coef[c] = a;
        coef[64 + c] = b[c] - mean * a;
    }
}

__global__ void k_adp(const float* __restrict__ feat, const float* __restrict__ Wa,
                      float* __restrict__ adp, int n) {
    __shared__ float w[192];
    if (threadIdx.x < 192) w[threadIdx.x] = Wa[threadIdx.x];
    __syncthreads();
    int row = blockIdx.x * blockDim.x + threadIdx.x;
    if (row >= n) return;
    float s0 = 0.f, s1 = 0.f, s2 = 0.f;
    const float* f = feat + (size_t)row * 64;
#pragma unroll 16
    for (int c = 0; c < 64; ++c) {
        float v = f[c];
        s0 += v * w[c * 3 + 0];
        s1 += v * w[c * 3 + 1];
        s2 += v * w[c * 3 + 2];
    }
    float m = fmaxf(s0, fmaxf(s1, s2));
    float e0 = expf(s0 - m), e1 = expf(s1 - m), e2 = expf(s2 - m);
    float inv = 1.f / (e0 + e1 + e2);
    adp[(size_t)row * 3 + 0] = e0 * inv;
    adp[(size_t)row * 3 + 1] = e1 * inv;
    adp[(size_t)row * 3 + 2] = e2 * inv;
}

__global__ void k_bnrelu_segsum(float* __restrict__ P, const float* __restrict__ coef,
                                const int* __restrict__ cl, float* __restrict__ seg,
                                float* __restrict__ cnt, int n) {
    __shared__ float sc[128];
    if (threadIdx.x < 128) sc[threadIdx.x] = coef[threadIdx.x];
    __syncthreads();
    int row = blockIdx.x * blockDim.x + threadIdx.x;
    if (row >= n) return;
    int c = cl[row];
    float* p = P + (size_t)row * 64;
    float* s = seg + (size_t)c * 64;
#pragma unroll
    for (int c4 = 0; c4 < 16; ++c4) {
        float4 x = *(float4*)(p + c4 * 4);
        x.x = fmaxf(x.x * sc[c4 * 4 + 0] + sc[64 + c4 * 4 + 0], 0.f);
        x.y = fmaxf(x.y * sc[c4 * 4 + 1] + sc[64 + c4 * 4 + 1], 0.f);
        x.z = fmaxf(x.z * sc[c4 * 4 + 2] + sc[64 + c4 * 4 + 2], 0.f);
        x.w = fmaxf(x.w * sc[c4 * 4 + 3] + sc[64 + c4 * 4 + 3], 0.f);
        *(float4*)(p + c4 * 4) = x;
        atomicAdd(s + c4 * 4 + 0, x.x);
        atomicAdd(s + c4 * 4 + 1, x.y);
        atomicAdd(s + c4 * 4 + 2, x.z);
        atomicAdd(s + c4 * 4 + 3, x.w);
    }
    atomicAdd(&cnt[c], 1.f);
}

__global__ void k_exp_segsum(float* __restrict__ P, const int* __restrict__ cl,
                             float* __restrict__ seg, const unsigned* __restrict__ mb,
                             int n) {
    int row = blockIdx.x * blockDim.x + threadIdx.x;
    if (row >= n) return;
    float mx = fmax_unmap(*mb);
    int c = cl[row];
    float* p = P + (size_t)row * 64;
    float* s = seg + (size_t)c * 64;
#pragma unroll
    for (int c4 = 0; c4 < 16; ++c4) {
        float4 x = *(float4*)(p + c4 * 4);
        x.x = expf(x.x - mx); x.y = expf(x.y - mx);
        x.z = expf(x.z - mx); x.w = expf(x.w - mx);
        *(float4*)(p + c4 * 4) = x;
        atomicAdd(s + c4 * 4 + 0, x.x);
        atomicAdd(s + c4 * 4 + 1, x.y);
        atomicAdd(s + c4 * 4 + 2, x.z);
        atomicAdd(s + c4 * 4 + 3, x.w);
    }
}

// pf = relu(bn(Q)) * P/(denom[cl]+1e-6); segA += pf  (pf never materialized)
__global__ void k_bnrelu_pw_segsum(const float* __restrict__ Q,
                                   const float* __restrict__ coef,
                                   const float* __restrict__ P,
                                   const float* __restrict__ den,
                                   const int* __restrict__ cl,
                                   float* __restrict__ seg, int n) {
    __shared__ float sc[128];
    if (threadIdx.x < 128) sc[threadIdx.x] = coef[threadIdx.x];
    __syncthreads();
    int row = blockIdx.x * blockDim.x + threadIdx.x;
    if (row >= n) return;
    int c = cl[row];
    const float* q = Q + (size_t)row * 64;
    const float* p = P + (size_t)row * 64;
    const float* d = den + (size_t)c * 64;
    float* s = seg + (size_t)c * 64;
#pragma unroll
    for (int c4 = 0; c4 < 16; ++c4) {
#pragma unroll
        for (int j = 0; j < 4; ++j) {
            int ch = c4 * 4 + j;
            float y = fmaxf(q[ch] * sc[ch] + sc[64 + ch], 0.f);
            float pf = y * p[ch] / (d[ch] + 1e-6f);
            atomicAdd(s + ch, pf);
        }
    }
}

__global__ void k_mix_accum(const float* __restrict__ seg, const int* __restrict__ cl,
                            const float* __restrict__ adp, int icol,
                            float* __restrict__ M, int n) {
    int row = blockIdx.x * blockDim.x + threadIdx.x;
    if (row >= n) return;
    float w = adp[(size_t)row * 3 + icol];
    int c = cl[row];
    const float* s = seg + (size_t)c * 64;
    float* m = M + (size_t)row * 64;
#pragma unroll
    for (int c4 = 0; c4 < 16; ++c4) {
        float4 mv = *(float4*)(m + c4 * 4);
        float4 sv = *(const float4*)(s + c4 * 4);
        mv.x += w * sv.x; mv.y += w * sv.y; mv.z += w * sv.z; mv.w += w * sv.w;
        *(float4*)(m + c4 * 4) = mv;
    }
}

__global__ void k_bnrelu(float* __restrict__ P, const float* __restrict__ coef, int n) {
    __shared__ float sc[128];
    if (threadIdx.x < 128) sc[threadIdx.x] = coef[threadIdx.x];
    __syncthreads();
    int row = blockIdx.x * blockDim.x + threadIdx.x;
    if (row >= n) return;
    float* p = P + (size_t)row * 64;
#pragma unroll
    for (int c4 = 0; c4 < 16; ++c4) {
        float4 x = *(float4*)(p + c4 * 4);
        x.x = fmaxf(x.x * sc[c4 * 4 + 0] + sc[64 + c4 * 4 + 0], 0.f);
        x.y = fmaxf(x.y * sc[c4 * 4 + 1] + sc[64 + c4 * 4 + 1], 0.f);
        x.z = fmaxf(x.z * sc[c4 * 4 + 2] + sc[64 + c4 * 4 + 2], 0.f);
        x.w = fmaxf(x.w * sc[c4 * 4 + 3] + sc[64 + c4 * 4 + 3], 0.f);
        *(float4*)(p + c4 * 4) = x;
    }
}

__global__ void k_bnrelu_add(float* __restrict__ F, const float* __restrict__ coef,
                             const float* __restrict__ feat, int n) {
    __shared__ float sc[128];
    if (threadIdx.x < 128) sc[threadIdx.x] = coef[threadIdx.x];
    __syncthreads();
    int row = blockIdx.x * blockDim.x + threadIdx.x;
    if (row >= n) return;
    float* f = F + (size_t)row * 64;
    const float* ft = feat + (size_t)row * 64;
#pragma unroll
    for (int c4 = 0; c4 < 16; ++c4) {
        float4 x = *(float4*)(f + c4 * 4);
        float4 r = *(const float4*)(ft + c4 * 4);
        x.x = fmaxf(x.x * sc[c4 * 4 + 0] + sc[64 + c4 * 4 + 0], 0.f) + r.x;
        x.y = fmaxf(x.y * sc[c4 * 4 + 1] + sc[64 + c4 * 4 + 1], 0.f) + r.y;
        x.z = fmaxf(x.z * sc[c4 * 4 + 2] + sc[64 + c4 * 4 + 2], 0.f) + r.z;
        x.w = fmaxf(x.w * sc[c4 * 4 + 3] + sc[64 + c4 * 4 + 3], 0.f) + r.w;
        *(float4*)(f + c4 * 4) = x;
    }
}

// out = relu(bn(H) + F)
__global__ void k_final(const float* __restrict__ H, const float* __restrict__ coef,
                        const float* __restrict__ F, float* __restrict__ out, int n) {
    __shared__ float sc[128];
    if (threadIdx.x < 128) sc[threadIdx.x] = coef[threadIdx.x];
    __syncthreads();
    int row = blockIdx.x * blockDim.x + threadIdx.x;
    if (row >= n) return;
    const float* h = H + (size_t)row * 64;
    const float* f = F + (size_t)row * 64;
    float* o = out + (size_t)row * 64;
#pragma unroll
    for (int c4 = 0; c4 < 16; ++c4) {
        float4 x = *(const float4*)(h + c4 * 4);
        float4 r = *(const float4*)(f + c4 * 4);
        x.x = fmaxf(x.x * sc[c4 * 4 + 0] + sc[64 + c4 * 4 + 0] + r.x, 0.f);
        x.y = fmaxf(x.y * sc[c4 * 4 + 1] + sc[64 + c4 * 4 + 1] + r.y, 0.f);
        x.z = fmaxf(x.z * sc[c4 * 4 + 2] + sc[64 + c4 * 4 + 2] + r.z, 0.f);
        x.w = fmaxf(x.w * sc[c4 * 4 + 3] + sc[64 + c4 * 4 + 3] + r.w, 0.f);
        *(float4*)(o + c4 * 4) = x;
    }
}

// ---------------------------------------------------------------------------
extern "C" void kernel_launch(void* const* d_in, const int* in_sizes, int n_in,
                              void* d_out, int out_size) {
    const float* feat   = (const float*)d_in[0];
    const int*   cl[3]  = {(const int*)d_in[1], (const int*)d_in[2], (const int*)d_in[3]};
    const int*   nbr    = (const int*)d_in[4];
    const float* W_lw   = (const float*)d_in[5];
    const float* g_lw   = (const float*)d_in[6];
    const float* b_lw   = (const float*)d_in[7];
    const float* W_w    = (const float*)d_in[8];
    const float* W_proj = (const float*)d_in[9];
    const float* g_proj = (const float*)d_in[10];
    const float* b_proj = (const float*)d_in[11];
    const float* W_adp  = (const float*)d_in[12];
    const float* W_fuse = (const float*)d_in[13];
    const float* g_fuse = (const float*)d_in[14];
    const float* b_fuse = (const float*)d_in[15];
    const float* W_c1   = (const float*)d_in[16];
    const float* g_c1   = (const float*)d_in[17];
    const float* b_c1   = (const float*)d_in[18];
    const float* W_c2   = (const float*)d_in[19];
    const float* g_c2   = (const float*)d_in[20];
    const float* b_c2   = (const float*)d_in[21];
    float* out = (float*)d_out;
    int n = in_sizes[1];   // cluster0 element count == N

    float *pP, *pQ, *pM, *pF, *pAdp, *pSegA, *pSegB, *pCnt, *pStats, *pCoef;
    unsigned* pMax;
    cudaGetSymbolAddress((void**)&pP, g_bufP);
    cudaGetSymbolAddress((void**)&pQ, g_bufQ);
    cudaGetSymbolAddress((void**)&pM, g_bufM);
    cudaGetSymbolAddress((void**)&pF, g_bufF);
    cudaGetSymbolAddress((void**)&pAdp, g_adp);
    cudaGetSymbolAddress((void**)&pSegA, g_segA);
    cudaGetSymbolAddress((void**)&pSegB, g_segB);
    cudaGetSymbolAddress((void**)&pCnt, g_cnt);
    cudaGetSymbolAddress((void**)&pStats, g_stats);
    cudaGetSymbolAddress((void**)&pCoef, g_coef);
    cudaGetSymbolAddress((void**)&pMax, g_maxbits);

    static const size_t NCLS[3] = {4096, 32768, 131072};
    const int GB = (n + 63) / 64;     // gemm/conv grid
    const int EB = (n + 255) / 256;   // elementwise grid

    cudaMemsetAsync(pM, 0, (size_t)n * 64 * sizeof(float));
    k_adp<<<EB, 256>>>(feat, W_adp, pAdp, n);

    for (int i = 0; i < 3; ++i) {
        size_t ncl = NCLS[i];
        cudaMemsetAsync(pStats, 0, 128 * sizeof(float));
        k_gemm_stats<<<GB, 64>>>(feat, W_lw + i * 4096, pP, pStats, n);
        k_bn_coef<<<1, 64>>>(pStats, g_lw + i * 64, b_lw + i * 64, pCoef, n);
        cudaMemsetAsync(pSegA, 0, ncl * 64 * sizeof(float));
        cudaMemsetAsync(pCnt, 0, ncl * sizeof(float));
        k_bnrelu_segsum<<<EB, 256>>>(pP, pCoef, cl[i], pSegA, pCnt, n);
        cudaMemsetAsync(pMax, 0, sizeof(unsigned));
        k_gemm_submean_max<<<GB, 64>>>(pP, W_w + i * 4096, pP, pSegA, pCnt,
                                       cl[i], pMax, n);
        cudaMemsetAsync(pSegB, 0, ncl * 64 * sizeof(float));
        k_exp_segsum<<<EB, 256>>>(pP, cl[i], pSegB, pMax, n);
        cudaMemsetAsync(pStats, 0, 128 * sizeof(float));
        k_gemm_stats<<<GB, 64>>>(feat, W_proj + i * 4096, pQ, pStats, n);
        k_bn_coef<<<1, 64>>>(pStats, g_proj + i * 64, b_proj + i * 64, pCoef, n);
        cudaMemsetAsync(pSegA, 0, ncl * 64 * sizeof(float));
        k_bnrelu_pw_segsum<<<EB, 256>>>(pQ, pCoef, pP, pSegB, cl[i], pSegA, n);
        k_mix_accum<<<EB, 256>>>(pSegA, cl[i], pAdp, i, pM, n);
    }

    // f_last = relu(bn(feat @ W_proj[3]))
    cudaMemsetAsync(pStats, 0, 128 * sizeof(float));
    k_gemm_stats<<<GB, 64>>>(feat, W_proj + 3 * 4096, pQ, pStats, n);
    k_bn_coef<<<1, 64>>>(pStats, g_proj + 192, b_proj + 192, pCoef, n);
    k_bnrelu<<<EB, 256>>>(pQ, pCoef, n);
    // fused = relu(bn([f_last, mix] @ W_fuse)) + feat
    cudaMemsetAsync(pStats, 0, 128 * sizeof(float));
    k_gemm2_stats<<<GB, 64>>>(pQ, pM, W_fuse, pF, pStats, n);
    k_bn_coef<<<1, 64>>>(pStats, g_fuse, b_fuse, pCoef, n);
    k_bnrelu_add<<<EB, 256>>>(pF, pCoef, feat, n);
    // conv1 -> bn -> relu
    cudaMemsetAsync(pStats, 0, 128 * sizeof(float));
    k_conv_stats<<<GB, 64>>>(pF, nbr, W_c1, pP, pStats, n);
    k_bn_coef<<<1, 64>>>(pStats, g_c1, b_c1, pCoef, n);
    k_bnrelu<<<EB, 256>>>(pP, pCoef, n);
    // conv2 -> bn ; out = relu(bn + fused)
    cudaMemsetAsync(pStats, 0, 128 * sizeof(float));
    k_conv_stats<<<GB, 64>>>(pP, nbr, W_c2, pQ, pStats, n);
    k_bn_coef<<<1, 64>>>(pStats, g_c2, b_c2, pCoef, n);
    k_final<<<EB, 256>>>(pQ, pCoef, pF, out, n);
}

// round 3
// speedup vs baseline: 1.3721x; 1.3721x over previous
#include <cuda_runtime.h>
#include <cuda_bf16.h>

// ---------------------------------------------------------------------------
// OACNNs block. Round 2: all matmuls (10 GEMMs + 2 K=27 gather convs) moved to
// bf16 tensor cores (mma.sync.m16n8k16) with 2-term bf16 split (3 MMAs:
// hi*hi + lo*hi + hi*lo) for ~fp32 accuracy. Segment scatters use
// red.global.add.v4.f32. BN-apply passes fused into GEMM/conv tile staging.
// ---------------------------------------------------------------------------

#define NPTS_MAX 500000
#define NCL_MAX  131072
#define TM 96          // rows per block (6 warps x 16)
#define NTHR 192

// scratch (device globals: allocation-free rule)
__device__ float    g_bufP[NPTS_MAX * 64];
__device__ float    g_bufQ[NPTS_MAX * 64];
__device__ float    g_bufM[NPTS_MAX * 64];
__device__ float    g_bufF[NPTS_MAX * 64];
__device__ float    g_adp [NPTS_MAX * 3];
__device__ float    g_segA[NCL_MAX * 64];
__device__ float    g_segB[NCL_MAX * 64];
__device__ float    g_cnt [NCL_MAX];
__device__ float    g_stats[128];   // [0:64) sum, [64:128) sumsq
__device__ float    g_coef [128];   // [0:64) scale a, [64:128) shift b
__device__ unsigned g_maxbits;

// ---------------- helpers ----------------
__device__ __forceinline__ unsigned fmax_map(float x) {
    unsigned b = __float_as_uint(x);
    return (b & 0x80000000u) ? ~b : (b | 0x80000000u);
}
__device__ __forceinline__ float fmax_unmap(unsigned u) {
    return (u & 0x80000000u) ? __uint_as_float(u & 0x7fffffffu)
                             : __uint_as_float(~u);
}
__device__ __forceinline__ void red_add_v4(float* addr, float4 v) {
    asm volatile("red.global.add.v4.f32 [%0], {%1,%2,%3,%4};"
                 :: "l"(addr), "f"(v.x), "f"(v.y), "f"(v.z), "f"(v.w)
                 : "memory");
}

// ---------------- tensor-core tile machinery ----------------
// Shared tile: A is TM x 64 (bf16 hi/lo planes, packed as bf16x2 in uint,
// row stride 36 uints = 72 bf16 -> conflict-free fragment loads).
// B stored n-major (Bst[n][k]) 64 x 64, same packing/stride.
struct __align__(16) SmemMMA {
    unsigned Ah[TM * 36];
    unsigned Al[TM * 36];
    unsigned Bh[64 * 36];
    unsigned Bl[64 * 36];
    float    csum[64], csq[64];
    float    coef[128];
    int      cls[TM];
    float    cinv[TM];
    unsigned smax;
};

__device__ __forceinline__ void mma16816(float* d, unsigned a0, unsigned a1,
                                         unsigned a2, unsigned a3,
                                         unsigned b0, unsigned b1) {
    asm volatile(
        "mma.sync.aligned.m16n8k16.row.col.f32.bf16.bf16.f32 "
        "{%0,%1,%2,%3}, {%4,%5,%6,%7}, {%8,%9}, {%0,%1,%2,%3};"
        : "+f"(d[0]), "+f"(d[1]), "+f"(d[2]), "+f"(d[3])
        : "r"(a0), "r"(a1), "r"(a2), "r"(a3), "r"(b0), "r"(b1));
}

__device__ __forceinline__ void split2(float x, float y, unsigned& h, unsigned& l) {
    __nv_bfloat16 hx = __float2bfloat16(x), hy = __float2bfloat16(y);
    float lx = x - __bfloat162float(hx);
    float ly = y - __bfloat162float(hy);
    __nv_bfloat162 hp; hp.x = hx; hp.y = hy;
    __nv_bfloat162 lp; lp.x = __float2bfloat16(lx); lp.y = __float2bfloat16(ly);
    h = *reinterpret_cast<unsigned*>(&hp);
    l = *reinterpret_cast<unsigned*>(&lp);
}

// store float4 (4 consecutive k) into A planes at (r, c4)
__device__ __forceinline__ void a_store(SmemMMA* s, int r, int c4, float4 v) {
    unsigned h0, l0, h1, l1;
    split2(v.x, v.y, h0, l0);
    split2(v.z, v.w, h1, l1);
    int w = r * 36 + c4 * 2;
    *reinterpret_cast<uint2*>(&s->Ah[w]) = make_uint2(h0, h1);
    *reinterpret_cast<uint2*>(&s->Al[w]) = make_uint2(l0, l1);
}

// stage B (one 64x64 weight tile, row-major [k][n] in gmem) -> n-major split
__device__ __forceinline__ void stage_B(SmemMMA* s, const float* __restrict__ Wk,
                                        int tid) {
#pragma unroll
    for (int it = 0; it < 11; ++it) {
        int idx = tid + it * NTHR;
        if (idx < 2048) {
            int cout = idx & 63, p = idx >> 6;   // p = k-pair 0..31
            float w0 = Wk[(2 * p) * 64 + cout];
            float w1 = Wk[(2 * p + 1) * 64 + cout];
            unsigned h, l;
            split2(w0, w1, h, l);
            s->Bh[cout * 36 + p] = h;
            s->Bl[cout * 36 + p] = l;
        }
    }
}

// the 96x64x64 (x3 split) mma sweep
__device__ __forceinline__ void mma_compute(SmemMMA* s, float acc[8][4],
                                            int wid, int lane) {
    int g = lane >> 2, c = lane & 3;
    int ar0 = (wid * 16 + g) * 36 + c;
    int ar1 = ar0 + 8 * 36;
#pragma unroll
    for (int kk = 0; kk < 4; ++kk) {
        int ko = kk * 8;
        unsigned a0h = s->Ah[ar0 + ko], a1h = s->Ah[ar1 + ko];
        unsigned a2h = s->Ah[ar0 + ko + 4], a3h = s->Ah[ar1 + ko + 4];
        unsigned a0l = s->Al[ar0 + ko], a1l = s->Al[ar1 + ko];
        unsigned a2l = s->Al[ar0 + ko + 4], a3l = s->Al[ar1 + ko + 4];
#pragma unroll
        for (int nt = 0; nt < 8; ++nt) {
            int bi = (nt * 8 + g) * 36 + ko + c;
            unsigned b0h = s->Bh[bi], b1h = s->Bh[bi + 4];
            unsigned b0l = s->Bl[bi], b1l = s->Bl[bi + 4];
            mma16816(acc[nt], a0h, a1h, a2h, a3h, b0h, b1h);
            mma16816(acc[nt], a0l, a1l, a2l, a3l, b0h, b1h);
            mma16816(acc[nt], a0h, a1h, a2h, a3h, b0l, b1l);
        }
    }
}

// store result + per-channel sum/sumsq
__device__ __forceinline__ void epilogue_stats(SmemMMA* s, float acc[8][4],
                                               float* __restrict__ Co,
                                               float* __restrict__ statsg,
                                               int row0, int n, int wid, int lane) {
    int g = lane >> 2, c = lane & 3;
    int r0 = row0 + wid * 16 + g, r1 = r0 + 8;
#pragma unroll
    for (int nt = 0; nt < 8; ++nt) {
        int ch = nt * 8 + 2 * c;
        if (r0 < n) *(float2*)(Co + (size_t)r0 * 64 + ch) = make_float2(acc[nt][0], acc[nt][1]);
        if (r1 < n) *(float2*)(Co + (size_t)r1 * 64 + ch) = make_float2(acc[nt][2], acc[nt][3]);
        atomicAdd(&s->csum[ch],     acc[nt][0] + acc[nt][2]);
        atomicAdd(&s->csum[ch + 1], acc[nt][1] + acc[nt][3]);
        atomicAdd(&s->csq[ch],      acc[nt][0] * acc[nt][0] + acc[nt][2] * acc[nt][2]);
        atomicAdd(&s->csq[ch + 1],  acc[nt][1] * acc[nt][1] + acc[nt][3] * acc[nt][3]);
    }
    __syncthreads();
    int tid = threadIdx.x;
    if (tid < 64)       atomicAdd(&statsg[tid], s->csum[tid]);
    else if (tid < 128) atomicAdd(&statsg[tid], s->csq[tid - 64]);
}

// ---------------- tensor-core kernels ----------------
// C = A @ W (64x64), fused per-channel stats
__global__ __launch_bounds__(NTHR)
void k_mma_gemm_stats(const float* __restrict__ A, const float* __restrict__ W,
                      float* __restrict__ Co, float* __restrict__ statsg, int n) {
    __shared__ SmemMMA s;
    int tid = threadIdx.x, wid = tid >> 5, lane = tid & 31;
    int row0 = blockIdx.x * TM;
    if (tid < 64) { s.csum[tid] = 0.f; s.csq[tid] = 0.f; }
    stage_B(&s, W, tid);
#pragma unroll
    for (int i = 0; i < 8; ++i) {
        int idx = tid + i * NTHR;
        int r = idx >> 4, c4 = idx & 15;
        int row = row0 + r;
        float4 v = make_float4(0.f, 0.f, 0.f, 0.f);
        if (row < n) v = *(const float4*)(A + (size_t)row * 64 + c4 * 4);
        a_store(&s, r, c4, v);
    }
    __syncthreads();
    float acc[8][4] = {};
    mma_compute(&s, acc, wid, lane);
    epilogue_stats(&s, acc, Co, statsg, row0, n, wid, lane);
}

// C = (relu(bn(P)) - mean[cl]) @ W, fused global-max of outputs. In-place ok.
__global__ __launch_bounds__(NTHR)
void k_mma_submean_max(const float* __restrict__ P, const float* __restrict__ coefg,
                       const float* __restrict__ W, const float* __restrict__ seg,
                       const float* __restrict__ cnt, const int* __restrict__ cl,
                       float* __restrict__ Co, unsigned* __restrict__ gmax, int n) {
    __shared__ SmemMMA s;
    int tid = threadIdx.x, wid = tid >> 5, lane = tid & 31;
    int row0 = blockIdx.x * TM;
    if (tid == 0) s.smax = 0u;
    if (tid < 128) s.coef[tid] = coefg[tid];
    if (tid < TM) {
        int row = row0 + tid;
        int c = (row < n) ? cl[row] : 0;
        s.cls[tid] = c;
        s.cinv[tid] = 1.f / fmaxf(cnt[c], 1.f);
    }
    stage_B(&s, W, tid);
    __syncthreads();
#pragma unroll
    for (int i = 0; i < 8; ++i) {
        int idx = tid + i * NTHR;
        int r = idx >> 4, c4 = idx & 15;
        int row = row0 + r;
        float4 v = make_float4(0.f, 0.f, 0.f, 0.f);
        if (row < n) {
            v = *(const float4*)(P + (size_t)row * 64 + c4 * 4);
            float4 ms = *(const float4*)(seg + (size_t)s.cls[r] * 64 + c4 * 4);
            float ci = s.cinv[r];
            int ch = c4 * 4;
            v.x = fmaxf(v.x * s.coef[ch + 0] + s.coef[64 + ch + 0], 0.f) - ms.x * ci;
            v.y = fmaxf(v.y * s.coef[ch + 1] + s.coef[64 + ch + 1], 0.f) - ms.y * ci;
            v.z = fmaxf(v.z * s.coef[ch + 2] + s.coef[64 + ch + 2], 0.f) - ms.z * ci;
            v.w = fmaxf(v.w * s.coef[ch + 3] + s.coef[64 + ch + 3], 0.f) - ms.w * ci;
        }
        a_store(&s, r, c4, v);
    }
    __syncthreads();
    float acc[8][4] = {};
    mma_compute(&s, acc, wid, lane);
    int g = lane >> 2, c = lane & 3;
    int r0 = row0 + wid * 16 + g, r1 = r0 + 8;
    unsigned lmax = 0u;
#pragma unroll
    for (int nt = 0; nt < 8; ++nt) {
        int ch = nt * 8 + 2 * c;
        if (r0 < n) {
            *(float2*)(Co + (size_t)r0 * 64 + ch) = make_float2(acc[nt][0], acc[nt][1]);
            lmax = max(lmax, max(fmax_map(acc[nt][0]), fmax_map(acc[nt][1])));
        }
        if (r1 < n) {
            *(float2*)(Co + (size_t)r1 * 64 + ch) = make_float2(acc[nt][2], acc[nt][3]);
            lmax = max(lmax, max(fmax_map(acc[nt][2]), fmax_map(acc[nt][3])));
        }
    }
    atomicMax(&s.smax, lmax);
    __syncthreads();
    if (tid == 0) atomicMax(gmax, s.smax);
}

// C = relu(bn(Q))@W[0:64] + M@W[64:128], fused stats (K=128 fuse GEMM)
__global__ __launch_bounds__(NTHR)
void k_mma_gemm2_stats(const float* __restrict__ Q, const float* __restrict__ coefg,
                       const float* __restrict__ M, const float* __restrict__ W,
                       float* __restrict__ Co, float* __restrict__ statsg, int n) {
    __shared__ SmemMMA s;
    int tid = threadIdx.x, wid = tid >> 5, lane = tid & 31;
    int row0 = blockIdx.x * TM;
    if (tid < 64) { s.csum[tid] = 0.f; s.csq[tid] = 0.f; }
    if (tid < 128) s.coef[tid] = coefg[tid];
    float acc[8][4] = {};
#pragma unroll
    for (int p = 0; p < 2; ++p) {
        __syncthreads();
        // B: k-rows p*64 .. p*64+63 of the 128x64 fuse weight
#pragma unroll
        for (int it = 0; it < 11; ++it) {
            int idx = tid + it * NTHR;
            if (idx < 2048) {
                int cout = idx & 63, pp = idx >> 6;
                float w0 = W[(p * 64 + 2 * pp) * 64 + cout];
                float w1 = W[(p * 64 + 2 * pp + 1) * 64 + cout];
                unsigned h, l;
                split2(w0, w1, h, l);
                s.Bh[cout * 36 + pp] = h;
                s.Bl[cout * 36 + pp] = l;
            }
        }
        const float* Ap = p ? M : Q;
#pragma unroll
        for (int i = 0; i < 8; ++i) {
            int idx = tid + i * NTHR;
            int r = idx >> 4, c4 = idx & 15;
            int row = row0 + r;
            float4 v = make_float4(0.f, 0.f, 0.f, 0.f);
            if (row < n) {
                v = *(const float4*)(Ap + (size_t)row * 64 + c4 * 4);
                if (p == 0) {
                    int ch = c4 * 4;
                    v.x = fmaxf(v.x * s.coef[ch + 0] + s.coef[64 + ch + 0], 0.f);
                    v.y = fmaxf(v.y * s.coef[ch + 1] + s.coef[64 + ch + 1], 0.f);
                    v.z = fmaxf(v.z * s.coef[ch + 2] + s.coef[64 + ch + 2], 0.f);
                    v.w = fmaxf(v.w * s.coef[ch + 3] + s.coef[64 + ch + 3], 0.f);
                }
            }
            a_store(&s, r, c4, v);
        }
        __syncthreads();
        mma_compute(&s, acc, wid, lane);
    }
    epilogue_stats(&s, acc, Co, statsg, row0, n, wid, lane);
}

// C = sum_k gather(A, nbr[:,k]) @ Wc[k]; optional bn-relu on gathered rows
__global__ __launch_bounds__(NTHR)
void k_mma_conv_stats(const float* __restrict__ A, const int* __restrict__ nbr,
                      const float* __restrict__ Wc, const float* __restrict__ coefg,
                      int use_coef, float* __restrict__ Co,
                      float* __restrict__ statsg, int n) {
    __shared__ SmemMMA s;
    int tid = threadIdx.x, wid = tid >> 5, lane = tid & 31;
    int row0 = blockIdx.x * TM;
    if (tid < 64) { s.csum[tid] = 0.f; s.csq[tid] = 0.f; }
    if (use_coef && tid < 128) s.coef[tid] = coefg[tid];
    float acc[8][4] = {};
    for (int k = 0; k < 27; ++k) {
        __syncthreads();
        stage_B(&s, Wc + k * 4096, tid);
#pragma unroll
        for (int i = 0; i < 8; ++i) {
            int idx = tid + i * NTHR;
            int r = idx >> 4, c4 = idx & 15;
            int row = row0 + r;
            float4 v = make_float4(0.f, 0.f, 0.f, 0.f);
            if (row < n) {
                int src = nbr[(size_t)row * 27 + k];
                v = *(const float4*)(A + (size_t)src * 64 + c4 * 4);
                if (use_coef) {
                    int ch = c4 * 4;
                    v.x = fmaxf(v.x * s.coef[ch + 0] + s.coef[64 + ch + 0], 0.f);
                    v.y = fmaxf(v.y * s.coef[ch + 1] + s.coef[64 + ch + 1], 0.f);
                    v.z = fmaxf(v.z * s.coef[ch + 2] + s.coef[64 + ch + 2], 0.f);
                    v.w = fmaxf(v.w * s.coef[ch + 3] + s.coef[64 + ch + 3], 0.f);
                }
            }
            a_store(&s, r, c4, v);
        }
        __syncthreads();
        mma_compute(&s, acc, wid, lane);
    }
    epilogue_stats(&s, acc, Co, statsg, row0, n, wid, lane);
}

// ---------------- small / elementwise kernels ----------------
__global__ void k_bn_coef(const float* __restrict__ stats,
                          const float* __restrict__ g, const float* __restrict__ b,
                          float* __restrict__ coef, int n) {
    int c = threadIdx.x;
    if (c < 64) {
        float inv_n = 1.f / (float)n;
        float mean = stats[c] * inv_n;
        float var = stats[64 + c] * inv_n - mean * mean;
        float a = g[c] * rsqrtf(var + 1e-3f);
        coef[c] = a;
        coef[64 + c] = b[c] - mean * a;
    }
}

__global__ void k_adp(const float* __restrict__ feat, const float* __restrict__ Wa,
                      float* __restrict__ adp, int n) {
    __shared__ float w[192];
    if (threadIdx.x < 192) w[threadIdx.x] = Wa[threadIdx.x];
    __syncthreads();
    int row = blockIdx.x * blockDim.x + threadIdx.x;
    if (row >= n) return;
    float s0 = 0.f, s1 = 0.f, s2 = 0.f;
    const float* f = feat + (size_t)row * 64;
#pragma unroll 16
    for (int c = 0; c < 64; ++c) {
        float v = f[c];
        s0 += v * w[c * 3 + 0];
        s1 += v * w[c * 3 + 1];
        s2 += v * w[c * 3 + 2];
    }
    float m = fmaxf(s0, fmaxf(s1, s2));
    float e0 = __expf(s0 - m), e1 = __expf(s1 - m), e2 = __expf(s2 - m);
    float inv = 1.f / (e0 + e1 + e2);
    adp[(size_t)row * 3 + 0] = e0 * inv;
    adp[(size_t)row * 3 + 1] = e1 * inv;
    adp[(size_t)row * 3 + 2] = e2 * inv;
}

// segsum of relu(bn(P)) without writing P back (consumer recomputes bn)
__global__ void k_segsum_bn(const float* __restrict__ P, const float* __restrict__ coef,
                            const int* __restrict__ cl, float* __restrict__ seg,
                            float* __restrict__ cnt, int n) {
    __shared__ float sc[128];
    if (threadIdx.x < 128) sc[threadIdx.x] = coef[threadIdx.x];
    __syncthreads();
    int row = blockIdx.x * blockDim.x + threadIdx.x;
    if (row >= n) return;
    int c = cl[row];
    const float* p = P + (size_t)row * 64;
    float* s = seg + (size_t)c * 64;
#pragma unroll
    for (int c4 = 0; c4 < 16; ++c4) {
        float4 x = *(const float4*)(p + c4 * 4);
        x.x = fmaxf(x.x * sc[c4 * 4 + 0] + sc[64 + c4 * 4 + 0], 0.f);
        x.y = fmaxf(x.y * sc[c4 * 4 + 1] + sc[64 + c4 * 4 + 1], 0.f);
        x.z = fmaxf(x.z * sc[c4 * 4 + 2] + sc[64 + c4 * 4 + 2], 0.f);
        x.w = fmaxf(x.w * sc[c4 * 4 + 3] + sc[64 + c4 * 4 + 3], 0.f);
        red_add_v4(s + c4 * 4, x);
    }
    atomicAdd(&cnt[c], 1.f);
}

__global__ void k_exp_segsum(float* __restrict__ P, const int* __restrict__ cl,
                             float* __restrict__ seg, const unsigned* __restrict__ mb,
                             int n) {
    int row = blockIdx.x * blockDim.x + threadIdx.x;
    if (row >= n) return;
    float mx = fmax_unmap(*mb);
    int c = cl[row];
    float* p = P + (size_t)row * 64;
    float* s = seg + (size_t)c * 64;
#pragma unroll
    for (int c4 = 0; c4 < 16; ++c4) {
        float4 x = *(float4*)(p + c4 * 4);
        x.x = __expf(x.x - mx); x.y = __expf(x.y - mx);
        x.z = __expf(x.z - mx); x.w = __expf(x.w - mx);
        *(float4*)(p + c4 * 4) = x;
        red_add_v4(s + c4 * 4, x);
    }
}

// pf = relu(bn(Q)) * P / (den[cl]+1e-6); seg += pf
__global__ void k_pw_segsum(const float* __restrict__ Q, const float* __restrict__ coef,
                            const float* __restrict__ P, const float* __restrict__ den,
                            const int* __restrict__ cl, float* __restrict__ seg, int n) {
    __shared__ float sc[128];
    if (threadIdx.x < 128) sc[threadIdx.x] = coef[threadIdx.x];
    __syncthreads();
    int row = blockIdx.x * blockDim.x + threadIdx.x;
    if (row >= n) return;
    int c = cl[row];
    const float* q = Q + (size_t)row * 64;
    const float* p = P + (size_t)row * 64;
    const float* d = den + (size_t)c * 64;
    float* s = seg + (size_t)c * 64;
#pragma unroll
    for (int c4 = 0; c4 < 16; ++c4) {
        float4 qv = *(const float4*)(q + c4 * 4);
        float4 pv = *(const float4*)(p + c4 * 4);
        float4 dv = *(const float4*)(d + c4 * 4);
        float4 o;
        o.x = fmaxf(qv.x * sc[c4 * 4 + 0] + sc[64 + c4 * 4 + 0], 0.f) * pv.x / (dv.x + 1e-6f);
        o.y = fmaxf(qv.y * sc[c4 * 4 + 1] + sc[64 + c4 * 4 + 1], 0.f) * pv.y / (dv.y + 1e-6f);
        o.z = fmaxf(qv.z * sc[c4 * 4 + 2] + sc[64 + c4 * 4 + 2], 0.f) * pv.z / (dv.z + 1e-6f);
        o.w = fmaxf(qv.w * sc[c4 * 4 + 3] + sc[64 + c4 * 4 + 3], 0.f) * pv.w / (dv.w + 1e-6f);
        red_add_v4(s + c4 * 4, o);
    }
}

__global__ void k_mix_accum(const float* __restrict__ seg, const int* __restrict__ cl,
                            const float* __restrict__ adp, int icol,
                            float* __restrict__ M, int n) {
    int row = blockIdx.x * blockDim.x + threadIdx.x;
    if (row >= n) return;
    float w = adp[(size_t)row * 3 + icol];
    int c = cl[row];
    const float* s = seg + (size_t)c * 64;
    float* m = M + (size_t)row * 64;
#pragma unroll
    for (int c4 = 0; c4 < 16; ++c4) {
        float4 mv = *(float4*)(m + c4 * 4);
        float4 sv = *(const float4*)(s + c4 * 4);
        mv.x += w * sv.x; mv.y += w * sv.y; mv.z += w * sv.z; mv.w += w * sv.w;
        *(float4*)(m + c4 * 4) = mv;
    }
}

__global__ void k_bnrelu_add(float* __restrict__ F, const float* __restrict__ coef,
                             const float* __restrict__ feat, int n) {
    __shared__ float sc[128];
    if (threadIdx.x < 128) sc[threadIdx.x] = coef[threadIdx.x];
    __syncthreads();
    int row = blockIdx.x * blockDim.x + threadIdx.x;
    if (row >= n) return;
    float* f = F + (size_t)row * 64;
    const float* ft = feat + (size_t)row * 64;
#pragma unroll
    for (int c4 = 0; c4 < 16; ++c4) {
        float4 x = *(float4*)(f + c4 * 4);
        float4 r = *(const float4*)(ft + c4 * 4);
        x.x = fmaxf(x.x * sc[c4 * 4 + 0] + sc[64 + c4 * 4 + 0], 0.f) + r.x;
        x.y = fmaxf(x.y * sc[c4 * 4 + 1] + sc[64 + c4 * 4 + 1], 0.f) + r.y;
        x.z = fmaxf(x.z * sc[c4 * 4 + 2] + sc[64 + c4 * 4 + 2], 0.f) + r.z;
        x.w = fmaxf(x.w * sc[c4 * 4 + 3] + sc[64 + c4 * 4 + 3], 0.f) + r.w;
        *(float4*)(f + c4 * 4) = x;
    }
}

__global__ void k_final(const float* __restrict__ H, const float* __restrict__ coef,
                        const float* __restrict__ F, float* __restrict__ out, int n) {
    __shared__ float sc[128];
    if (threadIdx.x < 128) sc[threadIdx.x] = coef[threadIdx.x];
    __syncthreads();
    int row = blockIdx.x * blockDim.x + threadIdx.x;
    if (row >= n) return;
    const float* h = H + (size_t)row * 64;
    const float* f = F + (size_t)row * 64;
    float* o = out + (size_t)row * 64;
#pragma unroll
    for (int c4 = 0; c4 < 16; ++c4) {
        float4 x = *(const float4*)(h + c4 * 4);
        float4 r = *(const float4*)(f + c4 * 4);
        x.x = fmaxf(x.x * sc[c4 * 4 + 0] + sc[64 + c4 * 4 + 0] + r.x, 0.f);
        x.y = fmaxf(x.y * sc[c4 * 4 + 1] + sc[64 + c4 * 4 + 1] + r.y, 0.f);
        x.z = fmaxf(x.z * sc[c4 * 4 + 2] + sc[64 + c4 * 4 + 2] + r.z, 0.f);
        x.w = fmaxf(x.w * sc[c4 * 4 + 3] + sc[64 + c4 * 4 + 3] + r.w, 0.f);
        *(float4*)(o + c4 * 4) = x;
    }
}

// ---------------------------------------------------------------------------
extern "C" void kernel_launch(void* const* d_in, const int* in_sizes, int n_in,
                              void* d_out, int out_size) {
    const float* feat   = (const float*)d_in[0];
    const int*   cl[3]  = {(const int*)d_in[1], (const int*)d_in[2], (const int*)d_in[3]};
    const int*   nbr    = (const int*)d_in[4];
    const float* W_lw   = (const float*)d_in[5];
    const float* g_lw   = (const float*)d_in[6];
    const float* b_lw   = (const float*)d_in[7];
    const float* W_w    = (const float*)d_in[8];
    const float* W_proj = (const float*)d_in[9];
    const float* g_proj = (const float*)d_in[10];
    const float* b_proj = (const float*)d_in[11];
    const float* W_adp  = (const float*)d_in[12];
    const float* W_fuse = (const float*)d_in[13];
    const float* g_fuse = (const float*)d_in[14];
    const float* b_fuse = (const float*)d_in[15];
    const float* W_c1   = (const float*)d_in[16];
    const float* g_c1   = (const float*)d_in[17];
    const float* b_c1   = (const float*)d_in[18];
    const float* W_c2   = (const float*)d_in[19];
    const float* g_c2   = (const float*)d_in[20];
    const float* b_c2   = (const float*)d_in[21];
    float* out = (float*)d_out;
    int n = in_sizes[1];

    float *pP, *pQ, *pM, *pF, *pAdp, *pSegA, *pSegB, *pCnt, *pStats, *pCoef;
    unsigned* pMax;
    cudaGetSymbolAddress((void**)&pP, g_bufP);
    cudaGetSymbolAddress((void**)&pQ, g_bufQ);
    cudaGetSymbolAddress((void**)&pM, g_bufM);
    cudaGetSymbolAddress((void**)&pF, g_bufF);
    cudaGetSymbolAddress((void**)&pAdp, g_adp);
    cudaGetSymbolAddress((void**)&pSegA, g_segA);
    cudaGetSymbolAddress((void**)&pSegB, g_segB);
    cudaGetSymbolAddress((void**)&pCnt, g_cnt);
    cudaGetSymbolAddress((void**)&pStats, g_stats);
    cudaGetSymbolAddress((void**)&pCoef, g_coef);
    cudaGetSymbolAddress((void**)&pMax, g_maxbits);

    static const size_t NCLS[3] = {4096, 32768, 131072};
    const int GB = (n + TM - 1) / TM;
    const int EB = (n + 255) / 256;

    cudaMemsetAsync(pM, 0, (size_t)n * 64 * sizeof(float));
    k_adp<<<EB, 256>>>(feat, W_adp, pAdp, n);

    for (int i = 0; i < 3; ++i) {
        size_t ncl = NCLS[i];
        cudaMemsetAsync(pStats, 0, 128 * sizeof(float));
        k_mma_gemm_stats<<<GB, NTHR>>>(feat, W_lw + i * 4096, pP, pStats, n);
        k_bn_coef<<<1, 64>>>(pStats, g_lw + i * 64, b_lw + i * 64, pCoef, n);
        cudaMemsetAsync(pSegA, 0, ncl * 64 * sizeof(float));
        cudaMemsetAsync(pCnt, 0, ncl * sizeof(float));
        k_segsum_bn<<<EB, 256>>>(pP, pCoef, cl[i], pSegA, pCnt, n);
        cudaMemsetAsync(pMax, 0, sizeof(unsigned));
        k_mma_submean_max<<<GB, NTHR>>>(pP, pCoef, W_w + i * 4096, pSegA, pCnt,
                                        cl[i], pP, pMax, n);
        cudaMemsetAsync(pSegB, 0, ncl * 64 * sizeof(float));
        k_exp_segsum<<<EB, 256>>>(pP, cl[i], pSegB, pMax, n);
        cudaMemsetAsync(pStats, 0, 128 * sizeof(float));
        k_mma_gemm_stats<<<GB, NTHR>>>(feat, W_proj + i * 4096, pQ, pStats, n);
        k_bn_coef<<<1, 64>>>(pStats, g_proj + i * 64, b_proj + i * 64, pCoef, n);
        cudaMemsetAsync(pSegA, 0, ncl * 64 * sizeof(float));
        k_pw_segsum<<<EB, 256>>>(pQ, pCoef, pP, pSegB, cl[i], pSegA, n);
        k_mix_accum<<<EB, 256>>>(pSegA, cl[i], pAdp, i, pM, n);
    }

    // f_last = relu(bn(feat @ W_proj[3]))   (bn applied inside gemm2 staging)
    cudaMemsetAsync(pStats, 0, 128 * sizeof(float));
    k_mma_gemm_stats<<<GB, NTHR>>>(feat, W_proj + 3 * 4096, pQ, pStats, n);
    k_bn_coef<<<1, 64>>>(pStats, g_proj + 192, b_proj + 192, pCoef, n);
    // fused = relu(bn([f_last, mix] @ W_fuse)) + feat
    cudaMemsetAsync(pStats, 0, 128 * sizeof(float));
    k_mma_gemm2_stats<<<GB, NTHR>>>(pQ, pCoef, pM, W_fuse, pF, pStats, n);
    k_bn_coef<<<1, 64>>>(pStats, g_fuse, b_fuse, pCoef, n);
    k_bnrelu_add<<<EB, 256>>>(pF, pCoef, feat, n);
    // conv1 (raw out in P) -> bn coef; conv2 applies bn-relu during gather
    cudaMemsetAsync(pStats, 0, 128 * sizeof(float));
    k_mma_conv_stats<<<GB, NTHR>>>(pF, nbr, W_c1, pCoef, 0, pP, pStats, n);
    k_bn_coef<<<1, 64>>>(pStats, g_c1, b_c1, pCoef, n);
    cudaMemsetAsync(pStats, 0, 128 * sizeof(float));
    k_mma_conv_stats<<<GB, NTHR>>>(pP, nbr, W_c2, pCoef, 1, pQ, pStats, n);
    k_bn_coef<<<1, 64>>>(pStats, g_c2, b_c2, pCoef, n);
    k_final<<<EB, 256>>>(pQ, pCoef, pF, out, n);
}

// round 4
// speedup vs baseline: 1.6467x; 1.2001x over previous
#include <cuda_runtime.h>
#include <cuda_bf16.h>

// ---------------------------------------------------------------------------
// OACNNs block, round 4.
//  - All weights pre-packed once into smem-image bf16 hi/lo planes (n-major,
//    144B stride) -> B staging is a raw copy.
//  - Activations pre-split once into bf16 hi/lo row planes -> A staging for
//    GEMMs/convs is a raw (gather-)copy via cp.async.
//  - Conv tap loop double-buffered with cp.async (overlap gather with MMA).
//  - mix (adp x segS) fused into the fuse-GEMM A staging.
// ---------------------------------------------------------------------------

#define NPTS_MAX 500000
#define NCL_MAX  131072
#define TM   128
#define NTHR 256
#define AS   36            // uints per A/B row (144B, conflict-free, 16B-aligned)
#define OFF_AL 4608        // TM*AS
#define OFF_B  9216        // 2*TM*AS
#define BUFU   13824       // uints per tile buffer (A hi/lo + B hi/lo)

// scratch (device globals: allocation-free rule)
__device__ float          g_bufP[NPTS_MAX * 64];
__device__ float          g_bufQ[NPTS_MAX * 64];
__device__ float          g_bufF[NPTS_MAX * 64];
__device__ __nv_bfloat162 g_pH[NPTS_MAX * 32];
__device__ __nv_bfloat162 g_pL[NPTS_MAX * 32];
__device__ float          g_segS0[NCL_MAX * 64];
__device__ float          g_segS1[NCL_MAX * 64];
__device__ float          g_segS2[NCL_MAX * 64];
__device__ float          g_segT[NCL_MAX * 64];
__device__ float          g_cnt [NCL_MAX];
__device__ float          g_adpv[NPTS_MAX * 3];
__device__ float          g_stats[128];
__device__ float          g_coefA[128];
__device__ float          g_coefB[128];
__device__ unsigned       g_maxbits;
__device__ unsigned       g_wpack[66 * 4608];

// ---------------- helpers ----------------
__device__ __forceinline__ unsigned fmax_map(float x) {
    unsigned b = __float_as_uint(x);
    return (b & 0x80000000u) ? ~b : (b | 0x80000000u);
}
__device__ __forceinline__ float fmax_unmap(unsigned u) {
    return (u & 0x80000000u) ? __uint_as_float(u & 0x7fffffffu)
                             : __uint_as_float(~u);
}
__device__ __forceinline__ void red_add_v4(float* addr, float4 v) {
    asm volatile("red.global.add.v4.f32 [%0], {%1,%2,%3,%4};"
                 :: "l"(addr), "f"(v.x), "f"(v.y), "f"(v.z), "f"(v.w)
                 : "memory");
}
__device__ __forceinline__ void cp16(unsigned* dst, const void* src, bool v) {
    unsigned d = (unsigned)__cvta_generic_to_shared(dst);
    int sz = v ? 16 : 0;
    asm volatile("cp.async.cg.shared.global [%0], [%1], 16, %2;"
                 :: "r"(d), "l"(src), "r"(sz) : "memory");
}
__device__ __forceinline__ void cp_commit() {
    asm volatile("cp.async.commit_group;" ::: "memory");
}
template <int N> __device__ __forceinline__ void cp_wait() {
    asm volatile("cp.async.wait_group %0;" :: "n"(N) : "memory");
}

__device__ __forceinline__ void split2(float x, float y, unsigned& h, unsigned& l) {
    __nv_bfloat16 hx = __float2bfloat16(x), hy = __float2bfloat16(y);
    float lx = x - __bfloat162float(hx);
    float ly = y - __bfloat162float(hy);
    __nv_bfloat162 hp; hp.x = hx; hp.y = hy;
    __nv_bfloat162 lp; lp.x = __float2bfloat16(lx); lp.y = __float2bfloat16(ly);
    h = *reinterpret_cast<unsigned*>(&hp);
    l = *reinterpret_cast<unsigned*>(&lp);
}

__device__ __forceinline__ void mma16816(float* d, unsigned a0, unsigned a1,
                                         unsigned a2, unsigned a3,
                                         unsigned b0, unsigned b1) {
    asm volatile(
        "mma.sync.aligned.m16n8k16.row.col.f32.bf16.bf16.f32 "
        "{%0,%1,%2,%3}, {%4,%5,%6,%7}, {%8,%9}, {%0,%1,%2,%3};"
        : "+f"(d[0]), "+f"(d[1]), "+f"(d[2]), "+f"(d[3])
        : "r"(a0), "r"(a1), "r"(a2), "r"(a3), "r"(b0), "r"(b1));
}

// conversion-path A store (split fp32 -> hi/lo planes in smem)
__device__ __forceinline__ void a_store(unsigned* buf, int r, int c4, float4 v) {
    unsigned h0, l0, h1, l1;
    split2(v.x, v.y, h0, l0);
    split2(v.z, v.w, h1, l1);
    int w = r * AS + c4 * 2;
    *reinterpret_cast<uint2*>(buf + w)          = make_uint2(h0, h1);
    *reinterpret_cast<uint2*>(buf + OFF_AL + w) = make_uint2(l0, l1);
}

// B staging = raw copy of a prepacked tile (hi plane then lo plane, 18432B)
__device__ __forceinline__ void stage_B_copy(unsigned* buf, const unsigned* tile, int tid) {
    const uint4* s = reinterpret_cast<const uint4*>(tile);
    for (int i = tid; i < 1152; i += NTHR) cp16(buf + OFF_B + i * 4, s + i, true);
}

// 128x64x64 (x3 split) mma sweep
__device__ __forceinline__ void mma_compute(const unsigned* buf, float acc[8][4],
                                            int wid, int lane) {
    const unsigned* Ah = buf;
    const unsigned* Al = buf + OFF_AL;
    const unsigned* Bh = buf + OFF_B;
    const unsigned* Bl = buf + OFF_B + 2304;
    int g = lane >> 2, c = lane & 3;
    int ar0 = (wid * 16 + g) * AS + c;
    int ar1 = ar0 + 8 * AS;
#pragma unroll
    for (int kk = 0; kk < 4; ++kk) {
        int ko = kk * 8;
        unsigned a0h = Ah[ar0 + ko], a1h = Ah[ar1 + ko];
        unsigned a2h = Ah[ar0 + ko + 4], a3h = Ah[ar1 + ko + 4];
        unsigned a0l = Al[ar0 + ko], a1l = Al[ar1 + ko];
        unsigned a2l = Al[ar0 + ko + 4], a3l = Al[ar1 + ko + 4];
#pragma unroll
        for (int nt = 0; nt < 8; ++nt) {
            int bi = (nt * 8 + g) * AS + ko + c;
            unsigned b0h = Bh[bi], b1h = Bh[bi + 4];
            unsigned b0l = Bl[bi], b1l = Bl[bi + 4];
            mma16816(acc[nt], a0h, a1h, a2h, a3h, b0h, b1h);
            mma16816(acc[nt], a0l, a1l, a2l, a3l, b0h, b1h);
            mma16816(acc[nt], a0h, a1h, a2h, a3h, b0l, b1l);
        }
    }
}

__device__ __forceinline__ void epilogue_stats(float acc[8][4], float* __restrict__ Co,
                                               float* __restrict__ statsg,
                                               float* csum, float* csq,
                                               int row0, int n, int wid, int lane, int tid) {
    int g = lane >> 2, c = lane & 3;
    int r0 = row0 + wid * 16 + g, r1 = r0 + 8;
#pragma unroll
    for (int nt = 0; nt < 8; ++nt) {
        int ch = nt * 8 + 2 * c;
        if (r0 < n) *(float2*)(Co + (size_t)r0 * 64 + ch) = make_float2(acc[nt][0], acc[nt][1]);
        if (r1 < n) *(float2*)(Co + (size_t)r1 * 64 + ch) = make_float2(acc[nt][2], acc[nt][3]);
        atomicAdd(&csum[ch],     acc[nt][0] + acc[nt][2]);
        atomicAdd(&csum[ch + 1], acc[nt][1] + acc[nt][3]);
        atomicAdd(&csq[ch],      acc[nt][0] * acc[nt][0] + acc[nt][2] * acc[nt][2]);
        atomicAdd(&csq[ch + 1],  acc[nt][1] * acc[nt][1] + acc[nt][3] * acc[nt][3]);
    }
    __syncthreads();
    if (tid < 64)       atomicAdd(&statsg[tid], csum[tid]);
    else if (tid < 128) atomicAdd(&statsg[tid], csq[tid - 64]);
}

// ---------------- prepack / split kernels ----------------
__global__ void k_prepack(const float* __restrict__ Wlw, const float* __restrict__ Ww,
                          const float* __restrict__ Wproj, const float* __restrict__ Wfuse,
                          const float* __restrict__ Wc1, const float* __restrict__ Wc2,
                          unsigned* __restrict__ pack) {
    int t = blockIdx.x;
    const float* src;
    if (t < 3)       src = Wlw  + t * 4096;
    else if (t < 6)  src = Ww   + (t - 3) * 4096;
    else if (t < 10) src = Wproj+ (t - 6) * 4096;
    else if (t < 12) src = Wfuse+ (t - 10) * 4096;
    else if (t < 39) src = Wc1  + (t - 12) * 4096;
    else             src = Wc2  + (t - 39) * 4096;
    unsigned* ph = pack + (size_t)t * 4608;
    unsigned* pl = ph + 2304;
    for (int idx = threadIdx.x; idx < 2048; idx += 256) {
        int cout = idx & 63, p = idx >> 6;
        unsigned h, l;
        split2(src[2 * p * 64 + cout], src[(2 * p + 1) * 64 + cout], h, l);
        ph[cout * AS + p] = h;
        pl[cout * AS + p] = l;
    }
}

// split fp32 -> bf16 hi/lo planes (plain)
__global__ void k_split(const float* __restrict__ A, __nv_bfloat162* __restrict__ H,
                        __nv_bfloat162* __restrict__ L, int total4) {
    int i = blockIdx.x * 256 + threadIdx.x;
    if (i >= total4) return;
    float4 v = ((const float4*)A)[i];
    unsigned h0, l0, h1, l1;
    split2(v.x, v.y, h0, l0);
    split2(v.z, v.w, h1, l1);
    ((uint2*)H)[i] = make_uint2(h0, h1);
    ((uint2*)L)[i] = make_uint2(l0, l1);
}

// F = relu(bn(rawF)) + feat; also emit bf16 planes of F
__global__ void k_bnrelu_add_split(float* __restrict__ F, const float* __restrict__ coef,
                                   const float* __restrict__ feat,
                                   __nv_bfloat162* __restrict__ H,
                                   __nv_bfloat162* __restrict__ L, int total4) {
    __shared__ float sc[128];
    if (threadIdx.x < 128) sc[threadIdx.x] = coef[threadIdx.x];
    __syncthreads();
    int i = blockIdx.x * 256 + threadIdx.x;
    if (i >= total4) return;
    int ch = (i & 15) * 4;
    float4 x = ((const float4*)F)[i];
    float4 r = ((const float4*)feat)[i];
    x.x = fmaxf(x.x * sc[ch + 0] + sc[64 + ch + 0], 0.f) + r.x;
    x.y = fmaxf(x.y * sc[ch + 1] + sc[64 + ch + 1], 0.f) + r.y;
    x.z = fmaxf(x.z * sc[ch + 2] + sc[64 + ch + 2], 0.f) + r.z;
    x.w = fmaxf(x.w * sc[ch + 3] + sc[64 + ch + 3], 0.f) + r.w;
    ((float4*)F)[i] = x;
    unsigned h0, l0, h1, l1;
    split2(x.x, x.y, h0, l0);
    split2(x.z, x.w, h1, l1);
    ((uint2*)H)[i] = make_uint2(h0, h1);
    ((uint2*)L)[i] = make_uint2(l0, l1);
}

// planes = split(relu(bn(P)))
__global__ void k_bnrelu_split(const float* __restrict__ P, const float* __restrict__ coef,
                               __nv_bfloat162* __restrict__ H,
                               __nv_bfloat162* __restrict__ L, int total4) {
    __shared__ float sc[128];
    if (threadIdx.x < 128) sc[threadIdx.x] = coef[threadIdx.x];
    __syncthreads();
    int i = blockIdx.x * 256 + threadIdx.x;
    if (i >= total4) return;
    int ch = (i & 15) * 4;
    float4 x = ((const float4*)P)[i];
    x.x = fmaxf(x.x * sc[ch + 0] + sc[64 + ch + 0], 0.f);
    x.y = fmaxf(x.y * sc[ch + 1] + sc[64 + ch + 1], 0.f);
    x.z = fmaxf(x.z * sc[ch + 2] + sc[64 + ch + 2], 0.f);
    x.w = fmaxf(x.w * sc[ch + 3] + sc[64 + ch + 3], 0.f);
    unsigned h0, l0, h1, l1;
    split2(x.x, x.y, h0, l0);
    split2(x.z, x.w, h1, l1);
    ((uint2*)H)[i] = make_uint2(h0, h1);
    ((uint2*)L)[i] = make_uint2(l0, l1);
}

// ---------------- tensor-core kernels ----------------
// copy-path GEMM: Co = A@W + stats (A from bf16 planes, W prepacked)
__global__ __launch_bounds__(NTHR)
void k_mma_gemmA(const uint4* __restrict__ AH, const uint4* __restrict__ AL,
                 const unsigned* __restrict__ tile, float* __restrict__ Co,
                 float* __restrict__ statsg, int n) {
    extern __shared__ unsigned buf[];
    __shared__ float csum[64], csq[64];
    int tid = threadIdx.x, wid = tid >> 5, lane = tid & 31;
    int row0 = blockIdx.x * TM;
    if (tid < 64) { csum[tid] = 0.f; csq[tid] = 0.f; }
    stage_B_copy(buf, tile, tid);
    {
        int row = tid >> 1, pl = tid & 1;
        int gr = row0 + row;
        bool v = gr < n;
        const uint4* s = (pl ? AL : AH) + (size_t)(v ? gr : 0) * 8;
        unsigned* d = buf + (pl ? OFF_AL : 0) + row * AS;
#pragma unroll
        for (int c = 0; c < 8; ++c) cp16(d + c * 4, s + c, v);
    }
    cp_commit();
    cp_wait<0>();
    __syncthreads();
    float acc[8][4] = {};
    mma_compute(buf, acc, wid, lane);
    epilogue_stats(acc, Co, statsg, csum, csq, row0, n, wid, lane, tid);
}

// gather conv, double-buffered cp.async over 27 taps; + stats
__global__ __launch_bounds__(NTHR)
void k_mma_conv(const uint4* __restrict__ AH, const uint4* __restrict__ AL,
                const int* __restrict__ nbr, const unsigned* __restrict__ pack,
                float* __restrict__ Co, float* __restrict__ statsg, int n) {
    extern __shared__ unsigned sm[];
    __shared__ float csum[64], csq[64];
    int tid = threadIdx.x, wid = tid >> 5, lane = tid & 31;
    int row0 = blockIdx.x * TM;
    int row = tid >> 1, pl = tid & 1;
    int gr = row0 + row;
    bool v = gr < n;
    const uint4* base = pl ? AL : AH;
    if (tid < 64) { csum[tid] = 0.f; csq[tid] = 0.f; }

    // prologue: issue tap 0
    {
        unsigned* b0 = sm;
        stage_B_copy(b0, pack, tid);
        int sr = v ? __ldg(&nbr[(size_t)gr * 27]) : 0;
        const uint4* s = base + (size_t)sr * 8;
        unsigned* d = b0 + (pl ? OFF_AL : 0) + row * AS;
#pragma unroll
        for (int c = 0; c < 8; ++c) cp16(d + c * 4, s + c, v);
        cp_commit();
    }
    float acc[8][4] = {};
    for (int k = 0; k < 27; ++k) {
        unsigned* cur = sm + (k & 1) * BUFU;
        if (k + 1 < 27) {
            unsigned* nb = sm + ((k + 1) & 1) * BUFU;
            stage_B_copy(nb, pack + (size_t)(k + 1) * 4608, tid);
            int sr = v ? __ldg(&nbr[(size_t)gr * 27 + k + 1]) : 0;
            const uint4* s = base + (size_t)sr * 8;
            unsigned* d = nb + (pl ? OFF_AL : 0) + row * AS;
#pragma unroll
            for (int c = 0; c < 8; ++c) cp16(d + c * 4, s + c, v);
            cp_commit();
            cp_wait<1>();
        } else {
            cp_wait<0>();
        }
        __syncthreads();
        mma_compute(cur, acc, wid, lane);
        __syncthreads();
    }
    epilogue_stats(acc, Co, statsg, csum, csq, row0, n, wid, lane, tid);
}

// conversion path: Co = (relu(bn(P)) - mean[cl]) @ W, fused global max. In-place.
__global__ __launch_bounds__(NTHR)
void k_mma_submean_max(const float* __restrict__ P, const float* __restrict__ coefg,
                       const unsigned* __restrict__ tile, const float* __restrict__ seg,
                       const float* __restrict__ cnt, const int* __restrict__ cl,
                       float* __restrict__ Co, unsigned* __restrict__ gmax, int n) {
    extern __shared__ unsigned buf[];
    __shared__ float coef[128];
    __shared__ int   cls[TM];
    __shared__ float cinv[TM];
    __shared__ unsigned smax;
    int tid = threadIdx.x, wid = tid >> 5, lane = tid & 31;
    int row0 = blockIdx.x * TM;
    if (tid == 0) smax = 0u;
    if (tid < 128) {
        coef[tid] = coefg[tid];
        int r = row0 + tid;
        int c = (r < n) ? cl[r] : 0;
        cls[tid] = c;
        cinv[tid] = 1.f / fmaxf(cnt[c], 1.f);
    }
    stage_B_copy(buf, tile, tid);
    cp_commit();
    __syncthreads();
#pragma unroll
    for (int i = 0; i < 8; ++i) {
        int idx = tid + i * NTHR;
        int r = idx >> 4, c4 = idx & 15;
        int grow = row0 + r;
        float4 vv = make_float4(0.f, 0.f, 0.f, 0.f);
        if (grow < n) {
            vv = *(const float4*)(P + (size_t)grow * 64 + c4 * 4);
            float4 ms = *(const float4*)(seg + (size_t)cls[r] * 64 + c4 * 4);
            float ci = cinv[r];
            int ch = c4 * 4;
            vv.x = fmaxf(vv.x * coef[ch + 0] + coef[64 + ch + 0], 0.f) - ms.x * ci;
            vv.y = fmaxf(vv.y * coef[ch + 1] + coef[64 + ch + 1], 0.f) - ms.y * ci;
            vv.z = fmaxf(vv.z * coef[ch + 2] + coef[64 + ch + 2], 0.f) - ms.z * ci;
            vv.w = fmaxf(vv.w * coef[ch + 3] + coef[64 + ch + 3], 0.f) - ms.w * ci;
        }
        a_store(buf, r, c4, vv);
    }
    cp_wait<0>();
    __syncthreads();
    float acc[8][4] = {};
    mma_compute(buf, acc, wid, lane);
    int g = lane >> 2, c = lane & 3;
    int r0 = row0 + wid * 16 + g, r1 = r0 + 8;
    unsigned lmax = 0u;
#pragma unroll
    for (int nt = 0; nt < 8; ++nt) {
        int ch = nt * 8 + 2 * c;
        if (r0 < n) {
            *(float2*)(Co + (size_t)r0 * 64 + ch) = make_float2(acc[nt][0], acc[nt][1]);
            lmax = max(lmax, max(fmax_map(acc[nt][0]), fmax_map(acc[nt][1])));
        }
        if (r1 < n) {
            *(float2*)(Co + (size_t)r1 * 64 + ch) = make_float2(acc[nt][2], acc[nt][3]);
            lmax = max(lmax, max(fmax_map(acc[nt][2]), fmax_map(acc[nt][3])));
        }
    }
    atomicMax(&smax, lmax);
    __syncthreads();
    if (tid == 0) atomicMax(gmax, smax);
}

// fuse GEMM: Co = relu(bn(Q))@Wf[0:64] + mix@Wf[64:128] + stats,
// mix = sum_i adp[:,i] * segS_i[cl_i]  (computed in staging, never materialized)
__global__ __launch_bounds__(NTHR)
void k_mma_gemm2(const float* __restrict__ Q, const float* __restrict__ coefg,
                 const unsigned* __restrict__ tiles,
                 const float* __restrict__ s0, const float* __restrict__ s1,
                 const float* __restrict__ s2,
                 const int* __restrict__ cl0, const int* __restrict__ cl1,
                 const int* __restrict__ cl2, const float* __restrict__ adp,
                 float* __restrict__ Co, float* __restrict__ statsg, int n) {
    extern __shared__ unsigned buf[];
    __shared__ float csum[64], csq[64];
    __shared__ float coef[128];
    __shared__ int   cls[3][TM];
    __shared__ float sad[3][TM];
    int tid = threadIdx.x, wid = tid >> 5, lane = tid & 31;
    int row0 = blockIdx.x * TM;
    if (tid < 64) { csum[tid] = 0.f; csq[tid] = 0.f; }
    if (tid < 128) {
        coef[tid] = coefg[tid];
        int r = row0 + tid;
        bool v = r < n;
        cls[0][tid] = v ? cl0[r] : 0;
        cls[1][tid] = v ? cl1[r] : 0;
        cls[2][tid] = v ? cl2[r] : 0;
        sad[0][tid] = v ? adp[(size_t)r * 3 + 0] : 0.f;
        sad[1][tid] = v ? adp[(size_t)r * 3 + 1] : 0.f;
        sad[2][tid] = v ? adp[(size_t)r * 3 + 2] : 0.f;
    }
    __syncthreads();
    float acc[8][4] = {};
#pragma unroll
    for (int p = 0; p < 2; ++p) {
        stage_B_copy(buf, tiles + (size_t)p * 4608, tid);
        cp_commit();
#pragma unroll
        for (int i = 0; i < 8; ++i) {
            int idx = tid + i * NTHR;
            int r = idx >> 4, c4 = idx & 15;
            int grow = row0 + r;
            float4 vv = make_float4(0.f, 0.f, 0.f, 0.f);
            if (grow < n) {
                if (p == 0) {
                    vv = *(const float4*)(Q + (size_t)grow * 64 + c4 * 4);
                    int ch = c4 * 4;
                    vv.x = fmaxf(vv.x * coef[ch + 0] + coef[64 + ch + 0], 0.f);
                    vv.y = fmaxf(vv.y * coef[ch + 1] + coef[64 + ch + 1], 0.f);
                    vv.z = fmaxf(vv.z * coef[ch + 2] + coef[64 + ch + 2], 0.f);
                    vv.w = fmaxf(vv.w * coef[ch + 3] + coef[64 + ch + 3], 0.f);
                } else {
                    float w0 = sad[0][r], w1 = sad[1][r], w2 = sad[2][r];
                    float4 a = *(const float4*)(s0 + (size_t)cls[0][r] * 64 + c4 * 4);
                    float4 b = *(const float4*)(s1 + (size_t)cls[1][r] * 64 + c4 * 4);
                    float4 cc = *(const float4*)(s2 + (size_t)cls[2][r] * 64 + c4 * 4);
                    vv.x = w0 * a.x + w1 * b.x + w2 * cc.x;
                    vv.y = w0 * a.y + w1 * b.y + w2 * cc.y;
                    vv.z = w0 * a.z + w1 * b.z + w2 * cc.z;
                    vv.w = w0 * a.w + w1 * b.w + w2 * cc.w;
                }
            }
            a_store(buf, r, c4, vv);
        }
        cp_wait<0>();
        __syncthreads();
        mma_compute(buf, acc, wid, lane);
        __syncthreads();
    }
    epilogue_stats(acc, Co, statsg, csum, csq, row0, n, wid, lane, tid);
}

// ---------------- small / elementwise kernels ----------------
__global__ void k_bn_coef(const float* __restrict__ stats,
                          const float* __restrict__ g, const float* __restrict__ b,
                          float* __restrict__ coef, int n) {
    int c = threadIdx.x;
    if (c < 64) {
        float inv_n = 1.f / (float)n;
        float mean = stats[c] * inv_n;
        float var = stats[64 + c] * inv_n - mean * mean;
        float a = g[c] * rsqrtf(var + 1e-3f);
        coef[c] = a;
        coef[64 + c] = b[c] - mean * a;
    }
}

__global__ void k_adp(const float* __restrict__ feat, const float* __restrict__ Wa,
                      float* __restrict__ adp, int n) {
    __shared__ float w[192];
    if (threadIdx.x < 192) w[threadIdx.x] = Wa[threadIdx.x];
    __syncthreads();
    int row = blockIdx.x * blockDim.x + threadIdx.x;
    if (row >= n) return;
    float s0 = 0.f, s1 = 0.f, s2 = 0.f;
    const float* f = feat + (size_t)row * 64;
#pragma unroll 16
    for (int c = 0; c < 64; ++c) {
        float v = f[c];
        s0 += v * w[c * 3 + 0];
        s1 += v * w[c * 3 + 1];
        s2 += v * w[c * 3 + 2];
    }
    float m = fmaxf(s0, fmaxf(s1, s2));
    float e0 = __expf(s0 - m), e1 = __expf(s1 - m), e2 = __expf(s2 - m);
    float inv = 1.f / (e0 + e1 + e2);
    adp[(size_t)row * 3 + 0] = e0 * inv;
    adp[(size_t)row * 3 + 1] = e1 * inv;
    adp[(size_t)row * 3 + 2] = e2 * inv;
}

__global__ void k_segsum_bn(const float* __restrict__ P, const float* __restrict__ coef,
                            const int* __restrict__ cl, float* __restrict__ seg,
                            float* __restrict__ cnt, int n) {
    __shared__ float sc[128];
    if (threadIdx.x < 128) sc[threadIdx.x] = coef[threadIdx.x];
    __syncthreads();
    int row = blockIdx.x * blockDim.x + threadIdx.x;
    if (row >= n) return;
    int c = cl[row];
    const float* p = P + (size_t)row * 64;
    float* s = seg + (size_t)c * 64;
#pragma unroll
    for (int c4 = 0; c4 < 16; ++c4) {
        float4 x = *(const float4*)(p + c4 * 4);
        x.x = fmaxf(x.x * sc[c4 * 4 + 0] + sc[64 + c4 * 4 + 0], 0.f);
        x.y = fmaxf(x.y * sc[c4 * 4 + 1] + sc[64 + c4 * 4 + 1], 0.f);
        x.z = fmaxf(x.z * sc[c4 * 4 + 2] + sc[64 + c4 * 4 + 2], 0.f);
        x.w = fmaxf(x.w * sc[c4 * 4 + 3] + sc[64 + c4 * 4 + 3], 0.f);
        red_add_v4(s + c4 * 4, x);
    }
    atomicAdd(&cnt[c], 1.f);
}

__global__ void k_exp_segsum(float* __restrict__ P, const int* __restrict__ cl,
                             float* __restrict__ seg, const unsigned* __restrict__ mb,
                             int n) {
    int row = blockIdx.x * blockDim.x + threadIdx.x;
    if (row >= n) return;
    float mx = fmax_unmap(*mb);
    int c = cl[row];
    float* p = P + (size_t)row * 64;
    float* s = seg + (size_t)c * 64;
#pragma unroll
    for (int c4 = 0; c4 < 16; ++c4) {
        float4 x = *(float4*)(p + c4 * 4);
        x.x = __expf(x.x - mx); x.y = __expf(x.y - mx);
        x.z = __expf(x.z - mx); x.w = __expf(x.w - mx);
        *(float4*)(p + c4 * 4) = x;
        red_add_v4(s + c4 * 4, x);
    }
}

__global__ void k_pw_segsum(const float* __restrict__ Q, const float* __restrict__ coef,
                            const float* __restrict__ P, const float* __restrict__ den,
                            const int* __restrict__ cl, float* __restrict__ seg, int n) {
    __shared__ float sc[128];
    if (threadIdx.x < 128) sc[threadIdx.x] = coef[threadIdx.x];
    __syncthreads();
    int row = blockIdx.x * blockDim.x + threadIdx.x;
    if (row >= n) return;
    int c = cl[row];
    const float* q = Q + (size_t)row * 64;
    const float* p = P + (size_t)row * 64;
    const float* d = den + (size_t)c * 64;
    float* s = seg + (size_t)c * 64;
#pragma unroll
    for (int c4 = 0; c4 < 16; ++c4) {
        float4 qv = *(const float4*)(q + c4 * 4);
        float4 pv = *(const float4*)(p + c4 * 4);
        float4 dv = *(const float4*)(d + c4 * 4);
        float4 o;
        o.x = fmaxf(qv.x * sc[c4 * 4 + 0] + sc[64 + c4 * 4 + 0], 0.f) * pv.x / (dv.x + 1e-6f);
        o.y = fmaxf(qv.y * sc[c4 * 4 + 1] + sc[64 + c4 * 4 + 1], 0.f) * pv.y / (dv.y + 1e-6f);
        o.z = fmaxf(qv.z * sc[c4 * 4 + 2] + sc[64 + c4 * 4 + 2], 0.f) * pv.z / (dv.z + 1e-6f);
        o.w = fmaxf(qv.w * sc[c4 * 4 + 3] + sc[64 + c4 * 4 + 3], 0.f) * pv.w / (dv.w + 1e-6f);
        red_add_v4(s + c4 * 4, o);
    }
}

__global__ void k_final(const float* __restrict__ H, const float* __restrict__ coef,
                        const float* __restrict__ F, float* __restrict__ out, int n) {
    __shared__ float sc[128];
    if (threadIdx.x < 128) sc[threadIdx.x] = coef[threadIdx.x];
    __syncthreads();
    int row = blockIdx.x * blockDim.x + threadIdx.x;
    if (row >= n) return;
    const float* h = H + (size_t)row * 64;
    const float* f = F + (size_t)row * 64;
    float* o = out + (size_t)row * 64;
#pragma unroll
    for (int c4 = 0; c4 < 16; ++c4) {
        float4 x = *(const float4*)(h + c4 * 4);
        float4 r = *(const float4*)(f + c4 * 4);
        x.x = fmaxf(x.x * sc[c4 * 4 + 0] + sc[64 + c4 * 4 + 0] + r.x, 0.f);
        x.y = fmaxf(x.y * sc[c4 * 4 + 1] + sc[64 + c4 * 4 + 1] + r.y, 0.f);
        x.z = fmaxf(x.z * sc[c4 * 4 + 2] + sc[64 + c4 * 4 + 2] + r.z, 0.f);
        x.w = fmaxf(x.w * sc[c4 * 4 + 3] + sc[64 + c4 * 4 + 3] + r.w, 0.f);
        *(float4*)(o + c4 * 4) = x;
    }
}

// ---------------------------------------------------------------------------
extern "C" void kernel_launch(void* const* d_in, const int* in_sizes, int n_in,
                              void* d_out, int out_size) {
    const float* feat   = (const float*)d_in[0];
    const int*   cl[3]  = {(const int*)d_in[1], (const int*)d_in[2], (const int*)d_in[3]};
    const int*   nbr    = (const int*)d_in[4];
    const float* W_lw   = (const float*)d_in[5];
    const float* g_lw   = (const float*)d_in[6];
    const float* b_lw   = (const float*)d_in[7];
    const float* W_w    = (const float*)d_in[8];
    const float* W_proj = (const float*)d_in[9];
    const float* g_proj = (const float*)d_in[10];
    const float* b_proj = (const float*)d_in[11];
    const float* W_adp  = (const float*)d_in[12];
    const float* W_fuse = (const float*)d_in[13];
    const float* g_fuse = (const float*)d_in[14];
    const float* b_fuse = (const float*)d_in[15];
    const float* W_c1   = (const float*)d_in[16];
    const float* g_c1   = (const float*)d_in[17];
    const float* b_c1   = (const float*)d_in[18];
    const float* W_c2   = (const float*)d_in[19];
    const float* g_c2   = (const float*)d_in[20];
    const float* b_c2   = (const float*)d_in[21];
    float* out = (float*)d_out;
    int n = in_sizes[1];

    float *pP, *pQ, *pF, *pS0, *pS1, *pS2, *pT, *pCnt, *pStats, *pCoefA, *pCoefB, *pAdp;
    __nv_bfloat162 *pH, *pL;
    unsigned *pMax, *pPack;
    cudaGetSymbolAddress((void**)&pP, g_bufP);
    cudaGetSymbolAddress((void**)&pQ, g_bufQ);
    cudaGetSymbolAddress((void**)&pF, g_bufF);
    cudaGetSymbolAddress((void**)&pH, g_pH);
    cudaGetSymbolAddress((void**)&pL, g_pL);
    cudaGetSymbolAddress((void**)&pS0, g_segS0);
    cudaGetSymbolAddress((void**)&pS1, g_segS1);
    cudaGetSymbolAddress((void**)&pS2, g_segS2);
    cudaGetSymbolAddress((void**)&pT, g_segT);
    cudaGetSymbolAddress((void**)&pCnt, g_cnt);
    cudaGetSymbolAddress((void**)&pStats, g_stats);
    cudaGetSymbolAddress((void**)&pCoefA, g_coefA);
    cudaGetSymbolAddress((void**)&pCoefB, g_coefB);
    cudaGetSymbolAddress((void**)&pAdp, g_adpv);
    cudaGetSymbolAddress((void**)&pMax, g_maxbits);
    cudaGetSymbolAddress((void**)&pPack, g_wpack);
    float* segS[3] = {pS0, pS1, pS2};

    static const size_t NCLS[3] = {4096, 32768, 131072};
    const int GB = (n + TM - 1) / TM;
    const int EB = (n + 255) / 256;
    const int total4 = n * 16;
    const int SB = (total4 + 255) / 256;
    const int SM1 = BUFU * 4;           // 55296B
    const int SM2 = BUFU * 8;           // 110592B

    cudaFuncSetAttribute(k_mma_gemmA, cudaFuncAttributeMaxDynamicSharedMemorySize, SM1);
    cudaFuncSetAttribute(k_mma_submean_max, cudaFuncAttributeMaxDynamicSharedMemorySize, SM1);
    cudaFuncSetAttribute(k_mma_gemm2, cudaFuncAttributeMaxDynamicSharedMemorySize, SM1);
    cudaFuncSetAttribute(k_mma_conv, cudaFuncAttributeMaxDynamicSharedMemorySize, SM2);

    const uint4* AH = (const uint4*)pH;
    const uint4* AL = (const uint4*)pL;

    k_prepack<<<66, 256>>>(W_lw, W_w, W_proj, W_fuse, W_c1, W_c2, pPack);
    k_split<<<SB, 256>>>(feat, pH, pL, total4);
    k_adp<<<EB, 256>>>(feat, W_adp, pAdp, n);

    for (int i = 0; i < 3; ++i) {
        size_t ncl = NCLS[i];
        cudaMemsetAsync(pStats, 0, 128 * sizeof(float));
        k_mma_gemmA<<<GB, NTHR, SM1>>>(AH, AL, pPack + (size_t)i * 4608, pP, pStats, n);
        k_bn_coef<<<1, 64>>>(pStats, g_lw + i * 64, b_lw + i * 64, pCoefA, n);
        cudaMemsetAsync(pT, 0, ncl * 64 * sizeof(float));
        cudaMemsetAsync(pCnt, 0, ncl * sizeof(float));
        k_segsum_bn<<<EB, 256>>>(pP, pCoefA, cl[i], pT, pCnt, n);
        cudaMemsetAsync(pMax, 0, sizeof(unsigned));
        k_mma_submean_max<<<GB, NTHR, SM1>>>(pP, pCoefA, pPack + (size_t)(3 + i) * 4608,
                                             pT, pCnt, cl[i], pP, pMax, n);
        cudaMemsetAsync(pT, 0, ncl * 64 * sizeof(float));
        k_exp_segsum<<<EB, 256>>>(pP, cl[i], pT, pMax, n);
        cudaMemsetAsync(pStats, 0, 128 * sizeof(float));
        k_mma_gemmA<<<GB, NTHR, SM1>>>(AH, AL, pPack + (size_t)(6 + i) * 4608, pQ, pStats, n);
        k_bn_coef<<<1, 64>>>(pStats, g_proj + i * 64, b_proj + i * 64, pCoefA, n);
        cudaMemsetAsync(segS[i], 0, ncl * 64 * sizeof(float));
        k_pw_segsum<<<EB, 256>>>(pQ, pCoefA, pP, pT, cl[i], segS[i], n);
    }

    // f_last = relu(bn(feat @ W_proj[3]))  (bn applied inside gemm2 staging)
    cudaMemsetAsync(pStats, 0, 128 * sizeof(float));
    k_mma_gemmA<<<GB, NTHR, SM1>>>(AH, AL, pPack + (size_t)9 * 4608, pQ, pStats, n);
    k_bn_coef<<<1, 64>>>(pStats, g_proj + 192, b_proj + 192, pCoefA, n);
    // fused = relu(bn([f_last, mix] @ W_fuse)) + feat   (mix fused in staging)
    cudaMemsetAsync(pStats, 0, 128 * sizeof(float));
    k_mma_gemm2<<<GB, NTHR, SM1>>>(pQ, pCoefA, pPack + (size_t)10 * 4608,
                                   pS0, pS1, pS2, cl[0], cl[1], cl[2], pAdp,
                                   pF, pStats, n);
    k_bn_coef<<<1, 64>>>(pStats, g_fuse, b_fuse, pCoefB, n);
    k_bnrelu_add_split<<<SB, 256>>>(pF, pCoefB, feat, pH, pL, total4);
    // conv1 -> bn coef; split; conv2; final
    cudaMemsetAsync(pStats, 0, 128 * sizeof(float));
    k_mma_conv<<<GB, NTHR, SM2>>>(AH, AL, nbr, pPack + (size_t)12 * 4608, pP, pStats, n);
    k_bn_coef<<<1, 64>>>(pStats, g_c1, b_c1, pCoefA, n);
    k_bnrelu_split<<<SB, 256>>>(pP, pCoefA, pH, pL, total4);
    cudaMemsetAsync(pStats, 0, 128 * sizeof(float));
    k_mma_conv<<<GB, NTHR, SM2>>>(AH, AL, nbr, pPack + (size_t)39 * 4608, pQ, pStats, n);
    k_bn_coef<<<1, 64>>>(pStats, g_c2, b_c2, pCoefB, n);
    k_final<<<EB, 256>>>(pQ, pCoefB, pF, out, n);
}

// round 6
// speedup vs baseline: 2.0986x; 1.2744x over previous
#include <cuda_runtime.h>
#include <cuda_bf16.h>

// ---------------------------------------------------------------------------
// OACNNs block, round 5.
//  - ldmatrix.x4 fragment loads (was scalar LDS -> L1-bound).
//  - 7 feat-GEMMs fused into one kernel (A staged once, B double-buffered).
//  - BN stats reduced via warp shuffles; BN coef computed inline in consumers.
// ---------------------------------------------------------------------------

#define NPTS_MAX 500000
#define NCL_MAX  131072
#define TM   128
#define NTHR 256
#define AS   36            // uints per row (144B stride, LDSM conflict-free)
#define OFF_AL 4608        // TM*AS   (A lo plane)
#define OFF_B  9216        // 2*TM*AS (B region within a tile buffer)
#define BUFU   13824       // uints per conv tile buffer (A hi/lo + B hi/lo)
#define ROWSZ  ((size_t)NPTS_MAX * 64)

// scratch (device globals: allocation-free rule)
__device__ float          g_bufs[7 * ROWSZ];     // P0,P1,P2,Q0,Q1,Q2,Q3
__device__ float          g_bufF[ROWSZ];
__device__ __nv_bfloat162 g_pH[NPTS_MAX * 32];
__device__ __nv_bfloat162 g_pL[NPTS_MAX * 32];
__device__ float          g_segS0[NCL_MAX * 64];
__device__ float          g_segS1[NCL_MAX * 64];
__device__ float          g_segS2[NCL_MAX * 64];
__device__ float          g_segT[NCL_MAX * 64];
__device__ float          g_cnt [NCL_MAX];
__device__ float          g_adpv[NPTS_MAX * 3];
__device__ float          g_statsA[10 * 128];    // 0-6 gemm7, 7 fuse, 8 c1, 9 c2
__device__ unsigned       g_maxbits;
__device__ unsigned       g_wpack[66 * 4608];

// ---------------- helpers ----------------
__device__ __forceinline__ unsigned fmax_map(float x) {
    unsigned b = __float_as_uint(x);
    return (b & 0x80000000u) ? ~b : (b | 0x80000000u);
}
__device__ __forceinline__ float fmax_unmap(unsigned u) {
    return (u & 0x80000000u) ? __uint_as_float(u & 0x7fffffffu)
                             : __uint_as_float(~u);
}
__device__ __forceinline__ void red_add_v4(float* addr, float4 v) {
    asm volatile("red.global.add.v4.f32 [%0], {%1,%2,%3,%4};"
                 :: "l"(addr), "f"(v.x), "f"(v.y), "f"(v.z), "f"(v.w)
                 : "memory");
}
__device__ __forceinline__ void cp16(unsigned* dst, const void* src, bool v) {
    unsigned d = (unsigned)__cvta_generic_to_shared(dst);
    int sz = v ? 16 : 0;
    asm volatile("cp.async.cg.shared.global [%0], [%1], 16, %2;"
                 :: "r"(d), "l"(src), "r"(sz) : "memory");
}
__device__ __forceinline__ void cp_commit() {
    asm volatile("cp.async.commit_group;" ::: "memory");
}
template <int N> __device__ __forceinline__ void cp_wait() {
    asm volatile("cp.async.wait_group %0;" :: "n"(N) : "memory");
}

__device__ __forceinline__ void split2(float x, float y, unsigned& h, unsigned& l) {
    __nv_bfloat16 hx = __float2bfloat16(x), hy = __float2bfloat16(y);
    float lx = x - __bfloat162float(hx);
    float ly = y - __bfloat162float(hy);
    __nv_bfloat162 hp; hp.x = hx; hp.y = hy;
    __nv_bfloat162 lp; lp.x = __float2bfloat16(lx); lp.y = __float2bfloat16(ly);
    h = *reinterpret_cast<unsigned*>(&hp);
    l = *reinterpret_cast<unsigned*>(&lp);
}

__device__ __forceinline__ void mma16816(float* d, unsigned a0, unsigned a1,
                                         unsigned a2, unsigned a3,
                                         unsigned b0, unsigned b1) {
    asm volatile(
        "mma.sync.aligned.m16n8k16.row.col.f32.bf16.bf16.f32 "
        "{%0,%1,%2,%3}, {%4,%5,%6,%7}, {%8,%9}, {%0,%1,%2,%3};"
        : "+f"(d[0]), "+f"(d[1]), "+f"(d[2]), "+f"(d[3])
        : "r"(a0), "r"(a1), "r"(a2), "r"(a3), "r"(b0), "r"(b1));
}
__device__ __forceinline__ void ldsm4(unsigned& r0, unsigned& r1, unsigned& r2,
                                      unsigned& r3, const unsigned* p) {
    unsigned a = (unsigned)__cvta_generic_to_shared(p);
    asm volatile("ldmatrix.sync.aligned.m8n8.x4.shared.b16 {%0,%1,%2,%3}, [%4];"
                 : "=r"(r0), "=r"(r1), "=r"(r2), "=r"(r3) : "r"(a));
}

// conversion-path A store (split fp32 -> hi/lo planes in smem)
__device__ __forceinline__ void a_store(unsigned* buf, int r, int c4, float4 v) {
    unsigned h0, l0, h1, l1;
    split2(v.x, v.y, h0, l0);
    split2(v.z, v.w, h1, l1);
    int w = r * AS + c4 * 2;
    *reinterpret_cast<uint2*>(buf + w)          = make_uint2(h0, h1);
    *reinterpret_cast<uint2*>(buf + OFF_AL + w) = make_uint2(l0, l1);
}

// B staging = raw cp.async copy of a prepacked tile (hi+lo, 18432B)
__device__ __forceinline__ void stage_B(unsigned* Bdst, const unsigned* tile, int tid) {
    const uint4* s = reinterpret_cast<const uint4*>(tile);
    for (int i = tid; i < 1152; i += NTHR) cp16(Bdst + i * 4, s + i, true);
}

// 128x64x64 (x3 split) mma sweep via ldmatrix
__device__ __forceinline__ void mma_compute(const unsigned* Areg, const unsigned* Breg,
                                            float acc[8][4], int wid, int lane) {
    const unsigned* Ah = Areg;
    const unsigned* Al = Areg + OFF_AL;
    const unsigned* Bh = Breg;
    const unsigned* Bl = Breg + 2304;
    int alr = lane & 15;
    int acol = (lane >> 4) * 4;
    const unsigned* aph = Ah + (wid * 16 + alr) * AS + acol;
    const unsigned* apl = Al + (wid * 16 + alr) * AS + acol;
    int brow = lane & 7;
    const unsigned* bp = ((lane & 16) ? Bl : Bh) + brow * AS + ((lane & 8) ? 4 : 0);
#pragma unroll
    for (int kk = 0; kk < 4; ++kk) {
        int ko = kk * 8;
        unsigned a0h, a1h, a2h, a3h, a0l, a1l, a2l, a3l;
        ldsm4(a0h, a1h, a2h, a3h, aph + ko);
        ldsm4(a0l, a1l, a2l, a3l, apl + ko);
#pragma unroll
        for (int nt = 0; nt < 8; ++nt) {
            unsigned b0h, b1h, b0l, b1l;
            ldsm4(b0h, b1h, b0l, b1l, bp + nt * 8 * AS + ko);
            mma16816(acc[nt], a0h, a1h, a2h, a3h, b0h, b1h);
            mma16816(acc[nt], a0l, a1l, a2l, a3l, b0h, b1h);
            mma16816(acc[nt], a0h, a1h, a2h, a3h, b0l, b1l);
        }
    }
}

// store result + shuffle-reduced per-channel sum/sumsq
__device__ __forceinline__ void epilogue_stats(float acc[8][4], float* __restrict__ Co,
                                               float* __restrict__ statsg,
                                               float* csum, float* csq,
                                               int row0, int n, int wid, int lane, int tid) {
    int g = lane >> 2, c = lane & 3;
    int r0 = row0 + wid * 16 + g, r1 = r0 + 8;
#pragma unroll
    for (int nt = 0; nt < 8; ++nt) {
        int ch = nt * 8 + 2 * c;
        if (r0 < n) *(float2*)(Co + (size_t)r0 * 64 + ch) = make_float2(acc[nt][0], acc[nt][1]);
        if (r1 < n) *(float2*)(Co + (size_t)r1 * 64 + ch) = make_float2(acc[nt][2], acc[nt][3]);
        float s0 = acc[nt][0] + acc[nt][2];
        float s1 = acc[nt][1] + acc[nt][3];
        float q0 = acc[nt][0] * acc[nt][0] + acc[nt][2] * acc[nt][2];
        float q1 = acc[nt][1] * acc[nt][1] + acc[nt][3] * acc[nt][3];
#pragma unroll
        for (int d = 4; d < 32; d <<= 1) {
            s0 += __shfl_xor_sync(0xffffffffu, s0, d);
            s1 += __shfl_xor_sync(0xffffffffu, s1, d);
            q0 += __shfl_xor_sync(0xffffffffu, q0, d);
            q1 += __shfl_xor_sync(0xffffffffu, q1, d);
        }
        if (lane < 4) {
            atomicAdd(&csum[ch], s0);
            atomicAdd(&csum[ch + 1], s1);
            atomicAdd(&csq[ch], q0);
            atomicAdd(&csq[ch + 1], q1);
        }
    }
    __syncthreads();
    if (tid < 64)       atomicAdd(&statsg[tid], csum[tid]);
    else if (tid < 128) atomicAdd(&statsg[tid], csq[tid - 64]);
}

// compute BN coef into smem[128] from raw stats (tid<64 does the work)
__device__ __forceinline__ void load_coef(float* sc, const float* __restrict__ stats,
                                          const float* __restrict__ g,
                                          const float* __restrict__ b, int n, int tid) {
    if (tid < 64) {
        float inv_n = 1.f / (float)n;
        float mean = stats[tid] * inv_n;
        float var = stats[64 + tid] * inv_n - mean * mean;
        float a = g[tid] * rsqrtf(var + 1e-3f);
        sc[tid] = a;
        sc[64 + tid] = b[tid] - mean * a;
    }
}

// ---------------- prepack / split kernels ----------------
__global__ void k_prepack(const float* __restrict__ Wlw, const float* __restrict__ Ww,
                          const float* __restrict__ Wproj, const float* __restrict__ Wfuse,
                          const float* __restrict__ Wc1, const float* __restrict__ Wc2,
                          unsigned* __restrict__ pack) {
    int t = blockIdx.x;
    const float* src;
    if (t < 3)       src = Wlw  + t * 4096;
    else if (t < 6)  src = Ww   + (t - 3) * 4096;
    else if (t < 10) src = Wproj+ (t - 6) * 4096;
    else if (t < 12) src = Wfuse+ (t - 10) * 4096;
    else if (t < 39) src = Wc1  + (t - 12) * 4096;
    else             src = Wc2  + (t - 39) * 4096;
    unsigned* ph = pack + (size_t)t * 4608;
    unsigned* pl = ph + 2304;
    for (int idx = threadIdx.x; idx < 2048; idx += 256) {
        int cout = idx & 63, p = idx >> 6;
        unsigned h, l;
        split2(src[2 * p * 64 + cout], src[(2 * p + 1) * 64 + cout], h, l);
        ph[cout * AS + p] = h;
        pl[cout * AS + p] = l;
    }
}

__global__ void k_split(const float* __restrict__ A, __nv_bfloat162* __restrict__ H,
                        __nv_bfloat162* __restrict__ L, int total4) {
    int i = blockIdx.x * 256 + threadIdx.x;
    if (i >= total4) return;
    float4 v = ((const float4*)A)[i];
    unsigned h0, l0, h1, l1;
    split2(v.x, v.y, h0, l0);
    split2(v.z, v.w, h1, l1);
    ((uint2*)H)[i] = make_uint2(h0, h1);
    ((uint2*)L)[i] = make_uint2(l0, l1);
}

// F = relu(bn(rawF)) + feat; also emit bf16 planes of F
__global__ void k_bnrelu_add_split(float* __restrict__ F, const float* __restrict__ stats,
                                   const float* __restrict__ g, const float* __restrict__ b,
                                   const float* __restrict__ feat,
                                   __nv_bfloat162* __restrict__ H,
                                   __nv_bfloat162* __restrict__ L, int n, int total4) {
    __shared__ float sc[128];
    load_coef(sc, stats, g, b, n, threadIdx.x);
    __syncthreads();
    int i = blockIdx.x * 256 + threadIdx.x;
    if (i >= total4) return;
    int ch = (i & 15) * 4;
    float4 x = ((const float4*)F)[i];
    float4 r = ((const float4*)feat)[i];
    x.x = fmaxf(x.x * sc[ch + 0] + sc[64 + ch + 0], 0.f) + r.x;
    x.y = fmaxf(x.y * sc[ch + 1] + sc[64 + ch + 1], 0.f) + r.y;
    x.z = fmaxf(x.z * sc[ch + 2] + sc[64 + ch + 2], 0.f) + r.z;
    x.w = fmaxf(x.w * sc[ch + 3] + sc[64 + ch + 3], 0.f) + r.w;
    ((float4*)F)[i] = x;
    unsigned h0, l0, h1, l1;
    split2(x.x, x.y, h0, l0);
    split2(x.z, x.w, h1, l1);
    ((uint2*)H)[i] = make_uint2(h0, h1);
    ((uint2*)L)[i] = make_uint2(l0, l1);
}

// planes = split(relu(bn(P)))
__global__ void k_bnrelu_split(const float* __restrict__ P, const float* __restrict__ stats,
                               const float* __restrict__ g, const float* __restrict__ b,
                               __nv_bfloat162* __restrict__ H,
                               __nv_bfloat162* __restrict__ L, int n, int total4) {
    __shared__ float sc[128];
    load_coef(sc, stats, g, b, n, threadIdx.x);
    __syncthreads();
    int i = blockIdx.x * 256 + threadIdx.x;
    if (i >= total4) return;
    int ch = (i & 15) * 4;
    float4 x = ((const float4*)P)[i];
    x.x = fmaxf(x.x * sc[ch + 0] + sc[64 + ch + 0], 0.f);
    x.y = fmaxf(x.y * sc[ch + 1] + sc[64 + ch + 1], 0.f);
    x.z = fmaxf(x.z * sc[ch + 2] + sc[64 + ch + 2], 0.f);
    x.w = fmaxf(x.w * sc[ch + 3] + sc[64 + ch + 3], 0.f);
    unsigned h0, l0, h1, l1;
    split2(x.x, x.y, h0, l0);
    split2(x.z, x.w, h1, l1);
    ((uint2*)H)[i] = make_uint2(h0, h1);
    ((uint2*)L)[i] = make_uint2(l0, l1);
}

// ---------------- tensor-core kernels ----------------
// 7 GEMMs sharing A=feat: stage A once, loop over 7 prepacked B tiles.
__global__ __launch_bounds__(NTHR)
void k_mma_gemm7(const uint4* __restrict__ AH, const uint4* __restrict__ AL,
                 const unsigned* __restrict__ pack,
                 float* __restrict__ o0, float* __restrict__ o1, float* __restrict__ o2,
                 float* __restrict__ o3, float* __restrict__ o4, float* __restrict__ o5,
                 float* __restrict__ o6, float* __restrict__ statsg, int n) {
    extern __shared__ unsigned sm[];     // A:[0,9216) B0:[9216,13824) B1:[13824,18432)
    __shared__ float csum[64], csq[64];
    float* Co[7] = {o0, o1, o2, o3, o4, o5, o6};
    const int tidx[7] = {0, 1, 2, 6, 7, 8, 9};
    int tid = threadIdx.x, wid = tid >> 5, lane = tid & 31;
    int row0 = blockIdx.x * TM;
    {   // stage A once
        int row = tid >> 1, pl = tid & 1;
        int gr = row0 + row;
        bool v = gr < n;
        const uint4* s = (pl ? AL : AH) + (size_t)(v ? gr : 0) * 8;
        unsigned* d = sm + (pl ? OFF_AL : 0) + row * AS;
#pragma unroll
        for (int c = 0; c < 8; ++c) cp16(d + c * 4, s + c, v);
    }
    stage_B(sm + OFF_B, pack + (size_t)tidx[0] * 4608, tid);
    cp_commit();
    for (int t = 0; t < 7; ++t) {
        unsigned* bcur = sm + OFF_B + (t & 1) * 4608;
        if (t + 1 < 7) {
            stage_B(sm + OFF_B + ((t + 1) & 1) * 4608, pack + (size_t)tidx[t + 1] * 4608, tid);
            cp_commit();
            cp_wait<1>();
        } else {
            cp_wait<0>();
        }
        if (tid < 64) { csum[tid] = 0.f; csq[tid] = 0.f; }
        __syncthreads();
        float acc[8][4] = {};
        mma_compute(sm, bcur, acc, wid, lane);
        epilogue_stats(acc, Co[t], statsg + t * 128, csum, csq, row0, n, wid, lane, tid);
        __syncthreads();
    }
}

// gather conv, double-buffered over 27 taps; + stats
__global__ __launch_bounds__(NTHR)
void k_mma_conv(const uint4* __restrict__ AH, const uint4* __restrict__ AL,
                const int* __restrict__ nbr, const unsigned* __restrict__ pack,
                float* __restrict__ Co, float* __restrict__ statsg, int n) {
    extern __shared__ unsigned sm[];
    __shared__ float csum[64], csq[64];
    int tid = threadIdx.x, wid = tid >> 5, lane = tid & 31;
    int row0 = blockIdx.x * TM;
    int row = tid >> 1, pl = tid & 1;
    int gr = row0 + row;
    bool v = gr < n;
    const uint4* base = pl ? AL : AH;
    if (tid < 64) { csum[tid] = 0.f; csq[tid] = 0.f; }
    {   // prologue: tap 0
        unsigned* b0 = sm;
        stage_B(b0 + OFF_B, pack, tid);
        int sr = v ? __ldg(&nbr[(size_t)gr * 27]) : 0;
        const uint4* s = base + (size_t)sr * 8;
        unsigned* d = b0 + (pl ? OFF_AL : 0) + row * AS;
#pragma unroll
        for (int c = 0; c < 8; ++c) cp16(d + c * 4, s + c, v);
        cp_commit();
    }
    float acc[8][4] = {};
    for (int k = 0; k < 27; ++k) {
        unsigned* cur = sm + (k & 1) * BUFU;
        if (k + 1 < 27) {
            unsigned* nb = sm + ((k + 1) & 1) * BUFU;
            stage_B(nb + OFF_B, pack + (size_t)(k + 1) * 4608, tid);
            int sr = v ? __ldg(&nbr[(size_t)gr * 27 + k + 1]) : 0;
            const uint4* s = base + (size_t)sr * 8;
            unsigned* d = nb + (pl ? OFF_AL : 0) + row * AS;
#pragma unroll
            for (int c = 0; c < 8; ++c) cp16(d + c * 4, s + c, v);
            cp_commit();
            cp_wait<1>();
        } else {
            cp_wait<0>();
        }
        __syncthreads();
        mma_compute(cur, cur + OFF_B, acc, wid, lane);
        __syncthreads();
    }
    epilogue_stats(acc, Co, statsg, csum, csq, row0, n, wid, lane, tid);
}

// Co = (relu(bn(P)) - mean[cl]) @ W, fused global max. In-place.
__global__ __launch_bounds__(NTHR)
void k_mma_submean_max(const float* __restrict__ P, const float* __restrict__ stats,
                       const float* __restrict__ gg, const float* __restrict__ bb,
                       const unsigned* __restrict__ tile, const float* __restrict__ seg,
                       const float* __restrict__ cnt, const int* __restrict__ cl,
                       float* __restrict__ Co, unsigned* __restrict__ gmax, int n) {
    extern __shared__ unsigned buf[];
    __shared__ float coef[128];
    __shared__ int   cls[TM];
    __shared__ float cinv[TM];
    __shared__ unsigned smax;
    int tid = threadIdx.x, wid = tid >> 5, lane = tid & 31;
    int row0 = blockIdx.x * TM;
    if (tid == 0) smax = 0u;
    load_coef(coef, stats, gg, bb, n, tid);
    if (tid < 128) {
        int r = row0 + tid;
        int c = (r < n) ? cl[r] : 0;
        cls[tid] = c;
        cinv[tid] = 1.f / fmaxf(cnt[c], 1.f);
    }
    stage_B(buf + OFF_B, tile, tid);
    cp_commit();
    __syncthreads();
#pragma unroll
    for (int i = 0; i < 8; ++i) {
        int idx = tid + i * NTHR;
        int r = idx >> 4, c4 = idx & 15;
        int grow = row0 + r;
        float4 vv = make_float4(0.f, 0.f, 0.f, 0.f);
        if (grow < n) {
            vv = *(const float4*)(P + (size_t)grow * 64 + c4 * 4);
            float4 ms = *(const float4*)(seg + (size_t)cls[r] * 64 + c4 * 4);
            float ci = cinv[r];
            int ch = c4 * 4;
            vv.x = fmaxf(vv.x * coef[ch + 0] + coef[64 + ch + 0], 0.f) - ms.x * ci;
            vv.y = fmaxf(vv.y * coef[ch + 1] + coef[64 + ch + 1], 0.f) - ms.y * ci;
            vv.z = fmaxf(vv.z * coef[ch + 2] + coef[64 + ch + 2], 0.f) - ms.z * ci;
            vv.w = fmaxf(vv.w * coef[ch + 3] + coef[64 + ch + 3], 0.f) - ms.w * ci;
        }
        a_store(buf, r, c4, vv);
    }
    cp_wait<0>();
    __syncthreads();
    float acc[8][4] = {};
    mma_compute(buf, buf + OFF_B, acc, wid, lane);
    int g = lane >> 2, c = lane & 3;
    int r0 = row0 + wid * 16 + g, r1 = r0 + 8;
    unsigned lmax = 0u;
#pragma unroll
    for (int nt = 0; nt < 8; ++nt) {
        int ch = nt * 8 + 2 * c;
        if (r0 < n) {
            *(float2*)(Co + (size_t)r0 * 64 + ch) = make_float2(acc[nt][0], acc[nt][1]);
            lmax = max(lmax, max(fmax_map(acc[nt][0]), fmax_map(acc[nt][1])));
        }
        if (r1 < n) {
            *(float2*)(Co + (size_t)r1 * 64 + ch) = make_float2(acc[nt][2], acc[nt][3]);
            lmax = max(lmax, max(fmax_map(acc[nt][2]), fmax_map(acc[nt][3])));
        }
    }
#pragma unroll
    for (int d = 1; d < 32; d <<= 1)
        lmax = max(lmax, __shfl_xor_sync(0xffffffffu, lmax, d));
    if (lane == 0) atomicMax(&smax, lmax);
    __syncthreads();
    if (tid == 0) atomicMax(gmax, smax);
}

// fuse GEMM: Co = relu(bn(Q))@Wf[0:64] + mix@Wf[64:128] + stats
__global__ __launch_bounds__(NTHR)
void k_mma_gemm2(const float* __restrict__ Q, const float* __restrict__ stats,
                 const float* __restrict__ gg, const float* __restrict__ bb,
                 const unsigned* __restrict__ tiles,
                 const float* __restrict__ s0, const float* __restrict__ s1,
                 const float* __restrict__ s2,
                 const int* __restrict__ cl0, const int* __restrict__ cl1,
                 const int* __restrict__ cl2, const float* __restrict__ adp,
                 float* __restrict__ Co, float* __restrict__ statsg, int n) {
    extern __shared__ unsigned buf[];
    __shared__ float csum[64], csq[64];
    __shared__ float coef[128];
    __shared__ int   cls[3][TM];
    __shared__ float sad[3][TM];
    int tid = threadIdx.x, wid = tid >> 5, lane = tid & 31;
    int row0 = blockIdx.x * TM;
    if (tid < 64) { csum[tid] = 0.f; csq[tid] = 0.f; }
    load_coef(coef, stats, gg, bb, n, tid);
    if (tid < 128) {
        int r = row0 + tid;
        bool v = r < n;
        cls[0][tid] = v ? cl0[r] : 0;
        cls[1][tid] = v ? cl1[r] : 0;
        cls[2][tid] = v ? cl2[r] : 0;
        sad[0][tid] = v ? adp[(size_t)r * 3 + 0] : 0.f;
        sad[1][tid] = v ? adp[(size_t)r * 3 + 1] : 0.f;
        sad[2][tid] = v ? adp[(size_t)r * 3 + 2] : 0.f;
    }
    __syncthreads();
    float acc[8][4] = {};
#pragma unroll
    for (int p = 0; p < 2; ++p) {
        stage_B(buf + OFF_B, tiles + (size_t)p * 4608, tid);
        cp_commit();
#pragma unroll
        for (int i = 0; i < 8; ++i) {
            int idx = tid + i * NTHR;
            int r = idx >> 4, c4 = idx & 15;
            int grow = row0 + r;
            float4 vv = make_float4(0.f, 0.f, 0.f, 0.f);
            if (grow < n) {
                if (p == 0) {
                    vv = *(const float4*)(Q + (size_t)grow * 64 + c4 * 4);
                    int ch = c4 * 4;
                    vv.x = fmaxf(vv.x * coef[ch + 0] + coef[64 + ch + 0], 0.f);
                    vv.y = fmaxf(vv.y * coef[ch + 1] + coef[64 + ch + 1], 0.f);
                    vv.z = fmaxf(vv.z * coef[ch + 2] + coef[64 + ch + 2], 0.f);
                    vv.w = fmaxf(vv.w * coef[ch + 3] + coef[64 + ch + 3], 0.f);
                } else {
                    float w0 = sad[0][r], w1 = sad[1][r], w2 = sad[2][r];
                    float4 a = *(const float4*)(s0 + (size_t)cls[0][r] * 64 + c4 * 4);
                    float4 bv = *(const float4*)(s1 + (size_t)cls[1][r] * 64 + c4 * 4);
                    float4 cc = *(const float4*)(s2 + (size_t)cls[2][r] * 64 + c4 * 4);
                    vv.x = w0 * a.x + w1 * bv.x + w2 * cc.x;
                    vv.y = w0 * a.y + w1 * bv.y + w2 * cc.y;
                    vv.z = w0 * a.z + w1 * bv.z + w2 * cc.z;
                    vv.w = w0 * a.w + w1 * bv.w + w2 * cc.w;
                }
            }
            a_store(buf, r, c4, vv);
        }
        cp_wait<0>();
        __syncthreads();
        mma_compute(buf, buf + OFF_B, acc, wid, lane);
        __syncthreads();
    }
    epilogue_stats(acc, Co, statsg, csum, csq, row0, n, wid, lane, tid);
}

// ---------------- small / elementwise kernels ----------------
__global__ void k_adp(const float* __restrict__ feat, const float* __restrict__ Wa,
                      float* __restrict__ adp, int n) {
    __shared__ float w[192];
    if (threadIdx.x < 192) w[threadIdx.x] = Wa[threadIdx.x];
    __syncthreads();
    int row = blockIdx.x * blockDim.x + threadIdx.x;
    if (row >= n) return;
    float s0 = 0.f, s1 = 0.f, s2 = 0.f;
    const float* f = feat + (size_t)row * 64;
#pragma unroll 16
    for (int c = 0; c < 64; ++c) {
        float v = f[c];
        s0 += v * w[c * 3 + 0];
        s1 += v * w[c * 3 + 1];
        s2 += v * w[c * 3 + 2];
    }
    float m = fmaxf(s0, fmaxf(s1, s2));
    float e0 = __expf(s0 - m), e1 = __expf(s1 - m), e2 = __expf(s2 - m);
    float inv = 1.f / (e0 + e1 + e2);
    adp[(size_t)row * 3 + 0] = e0 * inv;
    adp[(size_t)row * 3 + 1] = e1 * inv;
    adp[(size_t)row * 3 + 2] = e2 * inv;
}

__global__ void k_segsum_bn(const float* __restrict__ P, const float* __restrict__ stats,
                            const float* __restrict__ g, const float* __restrict__ b,
                            const int* __restrict__ cl, float* __restrict__ seg,
                            float* __restrict__ cnt, int n) {
    __shared__ float sc[128];
    load_coef(sc, stats, g, b, n, threadIdx.x);
    __syncthreads();
    int row = blockIdx.x * blockDim.x + threadIdx.x;
    if (row >= n) return;
    int c = cl[row];
    const float* p = P + (size_t)row * 64;
    float* s = seg + (size_t)c * 64;
#pragma unroll
    for (int c4 = 0; c4 < 16; ++c4) {
        float4 x = *(const float4*)(p + c4 * 4);
        x.x = fmaxf(x.x * sc[c4 * 4 + 0] + sc[64 + c4 * 4 + 0], 0.f);
        x.y = fmaxf(x.y * sc[c4 * 4 + 1] + sc[64 + c4 * 4 + 1], 0.f);
        x.z = fmaxf(x.z * sc[c4 * 4 + 2] + sc[64 + c4 * 4 + 2], 0.f);
        x.w = fmaxf(x.w * sc[c4 * 4 + 3] + sc[64 + c4 * 4 + 3], 0.f);
        red_add_v4(s + c4 * 4, x);
    }
    atomicAdd(&cnt[c], 1.f);
}

__global__ void k_exp_segsum(float* __restrict__ P, const int* __restrict__ cl,
                             float* __restrict__ seg, const unsigned* __restrict__ mb,
                             int n) {
    int row = blockIdx.x * blockDim.x + threadIdx.x;
    if (row >= n) return;
    float mx = fmax_unmap(*mb);
    int c = cl[row];
    float* p = P + (size_t)row * 64;
    float* s = seg + (size_t)c * 64;
#pragma unroll
    for (int c4 = 0; c4 < 16; ++c4) {
        float4 x = *(float4*)(p + c4 * 4);
        x.x = __expf(x.x - mx); x.y = __expf(x.y - mx);
        x.z = __expf(x.z - mx); x.w = __expf(x.w - mx);
        *(float4*)(p + c4 * 4) = x;
        red_add_v4(s + c4 * 4, x);
    }
}

__global__ void k_pw_segsum(const float* __restrict__ Q, const float* __restrict__ stats,
                            const float* __restrict__ g, const float* __restrict__ b,
                            const float* __restrict__ P, const float* __restrict__ den,
                            const int* __restrict__ cl, float* __restrict__ seg, int n) {
    __shared__ float sc[128];
    load_coef(sc, stats, g, b, n, threadIdx.x);
    __syncthreads();
    int row = blockIdx.x * blockDim.x + threadIdx.x;
    if (row >= n) return;
    int c = cl[row];
    const float* q = Q + (size_t)row * 64;
    const float* p = P + (size_t)row * 64;
    const float* d = den + (size_t)c * 64;
    float* s = seg + (size_t)c * 64;
#pragma unroll
    for (int c4 = 0; c4 < 16; ++c4) {
        float4 qv = *(const float4*)(q + c4 * 4);
        float4 pv = *(const float4*)(p + c4 * 4);
        float4 dv = *(const float4*)(d + c4 * 4);
        float4 o;
        o.x = fmaxf(qv.x * sc[c4 * 4 + 0] + sc[64 + c4 * 4 + 0], 0.f) * pv.x / (dv.x + 1e-6f);
        o.y = fmaxf(qv.y * sc[c4 * 4 + 1] + sc[64 + c4 * 4 + 1], 0.f) * pv.y / (dv.y + 1e-6f);
        o.z = fmaxf(qv.z * sc[c4 * 4 + 2] + sc[64 + c4 * 4 + 2], 0.f) * pv.z / (dv.z + 1e-6f);
        o.w = fmaxf(qv.w * sc[c4 * 4 + 3] + sc[64 + c4 * 4 + 3], 0.f) * pv.w / (dv.w + 1e-6f);
        red_add_v4(s + c4 * 4, o);
    }
}

// out = relu(bn(H) + F)
__global__ void k_final(const float* __restrict__ H, const float* __restrict__ stats,
                        const float* __restrict__ g, const float* __restrict__ b,
                        const float* __restrict__ F, float* __restrict__ out,
                        int n, int total4) {
    __shared__ float sc[128];
    load_coef(sc, stats, g, b, n, threadIdx.x);
    __syncthreads();
    int i = blockIdx.x * 256 + threadIdx.x;
    if (i >= total4) return;
    int ch = (i & 15) * 4;
    float4 x = ((const float4*)H)[i];
    float4 r = ((const float4*)F)[i];
    x.x = fmaxf(x.x * sc[ch + 0] + sc[64 + ch + 0] + r.x, 0.f);
    x.y = fmaxf(x.y * sc[ch + 1] + sc[64 + ch + 1] + r.y, 0.f);
    x.z = fmaxf(x.z * sc[ch + 2] + sc[64 + ch + 2] + r.z, 0.f);
    x.w = fmaxf(x.w * sc[ch + 3] + sc[64 + ch + 3] + r.w, 0.f);
    ((float4*)out)[i] = x;
}

// ---------------------------------------------------------------------------
extern "C" void kernel_launch(void* const* d_in, const int* in_sizes, int n_in,
                              void* d_out, int out_size) {
    const float* feat   = (const float*)d_in[0];
    const int*   cl[3]  = {(const int*)d_in[1], (const int*)d_in[2], (const int*)d_in[3]};
    const int*   nbr    = (const int*)d_in[4];
    const float* g_lw   = (const float*)d_in[6];
    const float* b_lw   = (const float*)d_in[7];
    const float* g_proj = (const float*)d_in[10];
    const float* b_proj = (const float*)d_in[11];
    const float* W_adp  = (const float*)d_in[12];
    const float* g_fuse = (const float*)d_in[14];
    const float* b_fuse = (const float*)d_in[15];
    const float* g_c1   = (const float*)d_in[17];
    const float* b_c1   = (const float*)d_in[18];
    const float* g_c2   = (const float*)d_in[20];
    const float* b_c2   = (const float*)d_in[21];
    float* out = (float*)d_out;
    int n = in_sizes[1];

    float *pBufs, *pF, *pS0, *pS1, *pS2, *pT, *pCnt, *pStats, *pAdp;
    __nv_bfloat162 *pH, *pL;
    unsigned *pMax, *pPack;
    cudaGetSymbolAddress((void**)&pBufs, g_bufs);
    cudaGetSymbolAddress((void**)&pF, g_bufF);
    cudaGetSymbolAddress((void**)&pH, g_pH);
    cudaGetSymbolAddress((void**)&pL, g_pL);
    cudaGetSymbolAddress((void**)&pS0, g_segS0);
    cudaGetSymbolAddress((void**)&pS1, g_segS1);
    cudaGetSymbolAddress((void**)&pS2, g_segS2);
    cudaGetSymbolAddress((void**)&pT, g_segT);
    cudaGetSymbolAddress((void**)&pCnt, g_cnt);
    cudaGetSymbolAddress((void**)&pStats, g_statsA);
    cudaGetSymbolAddress((void**)&pAdp, g_adpv);
    cudaGetSymbolAddress((void**)&pMax, g_maxbits);
    cudaGetSymbolAddress((void**)&pPack, g_wpack);
    float* Pb[3] = {pBufs, pBufs + ROWSZ, pBufs + 2 * ROWSZ};
    float* Qb[4] = {pBufs + 3 * ROWSZ, pBufs + 4 * ROWSZ, pBufs + 5 * ROWSZ,
                    pBufs + 6 * ROWSZ};
    float* segS[3] = {pS0, pS1, pS2};

    static const size_t NCLS[3] = {4096, 32768, 131072};
    const int GB = (n + TM - 1) / TM;
    const int EB = (n + 255) / 256;
    const int total4 = n * 16;
    const int SB = (total4 + 255) / 256;
    const int SM_G7 = 18432 * 4;        // 73728B
    const int SM_1  = BUFU * 4;         // 55296B
    const int SM_CV = BUFU * 8;         // 110592B

    cudaFuncSetAttribute(k_mma_gemm7, cudaFuncAttributeMaxDynamicSharedMemorySize, SM_G7);
    cudaFuncSetAttribute(k_mma_submean_max, cudaFuncAttributeMaxDynamicSharedMemorySize, SM_1);
    cudaFuncSetAttribute(k_mma_gemm2, cudaFuncAttributeMaxDynamicSharedMemorySize, SM_1);
    cudaFuncSetAttribute(k_mma_conv, cudaFuncAttributeMaxDynamicSharedMemorySize, SM_CV);

    const uint4* AH = (const uint4*)pH;
    const uint4* AL = (const uint4*)pL;
    const float* W_lw   = (const float*)d_in[5];
    const float* W_w    = (const float*)d_in[8];
    const float* W_proj = (const float*)d_in[9];
    const float* W_fuse = (const float*)d_in[13];
    const float* W_c1   = (const float*)d_in[16];
    const float* W_c2   = (const float*)d_in[19];

    k_prepack<<<66, 256>>>(W_lw, W_w, W_proj, W_fuse, W_c1, W_c2, pPack);
    k_split<<<SB, 256>>>(feat, pH, pL, total4);
    k_adp<<<EB, 256>>>(feat, W_adp, pAdp, n);

    // 7 feat-GEMMs in one kernel: P0,P1,P2 (lw), Q0,Q1,Q2 (proj), Q3 (proj3)
    cudaMemsetAsync(pStats, 0, 7 * 128 * sizeof(float));
    k_mma_gemm7<<<GB, NTHR, SM_G7>>>(AH, AL, pPack, Pb[0], Pb[1], Pb[2],
                                     Qb[0], Qb[1], Qb[2], Qb[3], pStats, n);

    for (int i = 0; i < 3; ++i) {
        size_t ncl = NCLS[i];
        cudaMemsetAsync(pT, 0, ncl * 64 * sizeof(float));
        cudaMemsetAsync(pCnt, 0, ncl * sizeof(float));
        k_segsum_bn<<<EB, 256>>>(Pb[i], pStats + i * 128, g_lw + i * 64, b_lw + i * 64,
                                 cl[i], pT, pCnt, n);
        cudaMemsetAsync(pMax, 0, sizeof(unsigned));
        k_mma_submean_max<<<GB, NTHR, SM_1>>>(Pb[i], pStats + i * 128, g_lw + i * 64,
                                              b_lw + i * 64, pPack + (size_t)(3 + i) * 4608,
                                              pT, pCnt, cl[i], Pb[i], pMax, n);
        cudaMemsetAsync(pT, 0, ncl * 64 * sizeof(float));
        k_exp_segsum<<<EB, 256>>>(Pb[i], cl[i], pT, pMax, n);
        cudaMemsetAsync(segS[i], 0, ncl * 64 * sizeof(float));
        k_pw_segsum<<<EB, 256>>>(Qb[i], pStats + (3 + i) * 128, g_proj + i * 64,
                                 b_proj + i * 64, Pb[i], pT, cl[i], segS[i], n);
    }

    // fused = relu(bn([relu(bn(Q3)), mix] @ W_fuse)) + feat
    cudaMemsetAsync(pStats + 7 * 128, 0, 128 * sizeof(float));
    k_mma_gemm2<<<GB, NTHR, SM_1>>>(Qb[3], pStats + 6 * 128, g_proj + 192, b_proj + 192,
                                    pPack + (size_t)10 * 4608, pS0, pS1, pS2,
                                    cl[0], cl[1], cl[2], pAdp, pF, pStats + 7 * 128, n);
    k_bnrelu_add_split<<<SB, 256>>>(pF, pStats + 7 * 128, g_fuse, b_fuse, feat,
                                    pH, pL, n, total4);
    // conv1 -> coef -> split ; conv2 -> final
    cudaMemsetAsync(pStats + 8 * 128, 0, 128 * sizeof(float));
    k_mma_conv<<<GB, NTHR, SM_CV>>>(AH, AL, nbr, pPack + (size_t)12 * 4608,
                                    Pb[0], pStats + 8 * 128, n);
    k_bnrelu_split<<<SB, 256>>>(Pb[0], pStats + 8 * 128, g_c1, b_c1, pH, pL, n, total4);
    cudaMemsetAsync(pStats + 9 * 128, 0, 128 * sizeof(float));
    k_mma_conv<<<GB, NTHR, SM_CV>>>(AH, AL, nbr, pPack + (size_t)39 * 4608,
                                    Qb[0], pStats + 9 * 128, n);
    k_final<<<SB, 256>>>(Qb[0], pStats + 9 * 128, g_c2, b_c2, pF, out, n, total4);
}

// round 7
// speedup vs baseline: 2.3177x; 1.1044x over previous
#include <cuda_runtime.h>
#include <cuda_bf16.h>

// ---------------------------------------------------------------------------
// OACNNs block, round 7.
//  - exp + denominator segsum fused into the submean GEMM epilogue (global-max
//    shift dropped: it cancels analytically; epsilon perturbation ~1e-5).
//  - feat split fused into gemm7 A-staging (k_split removed).
//  - 3 scales batched per launch (gridDim.y=3) with contiguous segment arenas.
// ---------------------------------------------------------------------------

#define NPTS_MAX 500000
#define SEGTOT   167936     // 4096 + 32768 + 131072
#define TM   128
#define NTHR 256
#define AS   36             // uints per row (144B stride, LDSM conflict-free)
#define OFF_AL 4608        // TM*AS   (A lo plane)
#define OFF_B  9216        // 2*TM*AS (B region within a tile buffer)
#define BUFU   13824       // uints per conv tile buffer (A hi/lo + B hi/lo)
#define ROWSZ  ((size_t)NPTS_MAX * 64)

// scratch (device globals: allocation-free rule)
__device__ float          g_bufs[7 * ROWSZ];     // P0,P1,P2,Q0,Q1,Q2,Q3
__device__ float          g_bufF[ROWSZ];
__device__ __nv_bfloat162 g_pH[NPTS_MAX * 32];
__device__ __nv_bfloat162 g_pL[NPTS_MAX * 32];
__device__ float          g_segMean[SEGTOT * 64];
__device__ float          g_segDen [SEGTOT * 64];
__device__ float          g_segS   [SEGTOT * 64];
__device__ float          g_cnt    [SEGTOT];
__device__ float          g_adpv[NPTS_MAX * 3];
__device__ float          g_statsA[10 * 128];    // 0-6 gemm7, 7 fuse, 8 c1, 9 c2
__device__ unsigned       g_wpack[66 * 4608];

__device__ __constant__ int c_soff[3] = {0, 4096, 36864};

// ---------------- helpers ----------------
__device__ __forceinline__ void red_add_v4(float* addr, float4 v) {
    asm volatile("red.global.add.v4.f32 [%0], {%1,%2,%3,%4};"
                 :: "l"(addr), "f"(v.x), "f"(v.y), "f"(v.z), "f"(v.w)
                 : "memory");
}
__device__ __forceinline__ void red_add_v2(float* addr, float x, float y) {
    asm volatile("red.global.add.v2.f32 [%0], {%1,%2};"
                 :: "l"(addr), "f"(x), "f"(y) : "memory");
}
__device__ __forceinline__ void cp16(unsigned* dst, const void* src, bool v) {
    unsigned d = (unsigned)__cvta_generic_to_shared(dst);
    int sz = v ? 16 : 0;
    asm volatile("cp.async.cg.shared.global [%0], [%1], 16, %2;"
                 :: "r"(d), "l"(src), "r"(sz) : "memory");
}
__device__ __forceinline__ void cp_commit() {
    asm volatile("cp.async.commit_group;" ::: "memory");
}
template <int N> __device__ __forceinline__ void cp_wait() {
    asm volatile("cp.async.wait_group %0;" :: "n"(N) : "memory");
}

__device__ __forceinline__ void split2(float x, float y, unsigned& h, unsigned& l) {
    __nv_bfloat16 hx = __float2bfloat16(x), hy = __float2bfloat16(y);
    float lx = x - __bfloat162float(hx);
    float ly = y - __bfloat162float(hy);
    __nv_bfloat162 hp; hp.x = hx; hp.y = hy;
    __nv_bfloat162 lp; lp.x = __float2bfloat16(lx); lp.y = __float2bfloat16(ly);
    h = *reinterpret_cast<unsigned*>(&hp);
    l = *reinterpret_cast<unsigned*>(&lp);
}

__device__ __forceinline__ void mma16816(float* d, unsigned a0, unsigned a1,
                                         unsigned a2, unsigned a3,
                                         unsigned b0, unsigned b1) {
    asm volatile(
        "mma.sync.aligned.m16n8k16.row.col.f32.bf16.bf16.f32 "
        "{%0,%1,%2,%3}, {%4,%5,%6,%7}, {%8,%9}, {%0,%1,%2,%3};"
        : "+f"(d[0]), "+f"(d[1]), "+f"(d[2]), "+f"(d[3])
        : "r"(a0), "r"(a1), "r"(a2), "r"(a3), "r"(b0), "r"(b1));
}
__device__ __forceinline__ void ldsm4(unsigned& r0, unsigned& r1, unsigned& r2,
                                      unsigned& r3, const unsigned* p) {
    unsigned a = (unsigned)__cvta_generic_to_shared(p);
    asm volatile("ldmatrix.sync.aligned.m8n8.x4.shared.b16 {%0,%1,%2,%3}, [%4];"
                 : "=r"(r0), "=r"(r1), "=r"(r2), "=r"(r3) : "r"(a));
}

__device__ __forceinline__ void a_store(unsigned* buf, int r, int c4, float4 v) {
    unsigned h0, l0, h1, l1;
    split2(v.x, v.y, h0, l0);
    split2(v.z, v.w, h1, l1);
    int w = r * AS + c4 * 2;
    *reinterpret_cast<uint2*>(buf + w)          = make_uint2(h0, h1);
    *reinterpret_cast<uint2*>(buf + OFF_AL + w) = make_uint2(l0, l1);
}

__device__ __forceinline__ void stage_B(unsigned* Bdst, const unsigned* tile, int tid) {
    const uint4* s = reinterpret_cast<const uint4*>(tile);
    for (int i = tid; i < 1152; i += NTHR) cp16(Bdst + i * 4, s + i, true);
}

// 128x64x64 (x3 split) mma sweep via ldmatrix
__device__ __forceinline__ void mma_compute(const unsigned* Areg, const unsigned* Breg,
                                            float acc[8][4], int wid, int lane) {
    const unsigned* Ah = Areg;
    const unsigned* Al = Areg + OFF_AL;
    const unsigned* Bh = Breg;
    const unsigned* Bl = Breg + 2304;
    int alr = lane & 15;
    int acol = (lane >> 4) * 4;
    const unsigned* aph = Ah + (wid * 16 + alr) * AS + acol;
    const unsigned* apl = Al + (wid * 16 + alr) * AS + acol;
    int brow = lane & 7;
    const unsigned* bp = ((lane & 16) ? Bl : Bh) + brow * AS + ((lane & 8) ? 4 : 0);
#pragma unroll
    for (int kk = 0; kk < 4; ++kk) {
        int ko = kk * 8;
        unsigned a0h, a1h, a2h, a3h, a0l, a1l, a2l, a3l;
        ldsm4(a0h, a1h, a2h, a3h, aph + ko);
        ldsm4(a0l, a1l, a2l, a3l, apl + ko);
#pragma unroll
        for (int nt = 0; nt < 8; ++nt) {
            unsigned b0h, b1h, b0l, b1l;
            ldsm4(b0h, b1h, b0l, b1l, bp + nt * 8 * AS + ko);
            mma16816(acc[nt], a0h, a1h, a2h, a3h, b0h, b1h);
            mma16816(acc[nt], a0l, a1l, a2l, a3l, b0h, b1h);
            mma16816(acc[nt], a0h, a1h, a2h, a3h, b0l, b1l);
        }
    }
}

__device__ __forceinline__ void epilogue_stats(float acc[8][4], float* __restrict__ Co,
                                               float* __restrict__ statsg,
                                               float* csum, float* csq,
                                               int row0, int n, int wid, int lane, int tid) {
    int g = lane >> 2, c = lane & 3;
    int r0 = row0 + wid * 16 + g, r1 = r0 + 8;
#pragma unroll
    for (int nt = 0; nt < 8; ++nt) {
        int ch = nt * 8 + 2 * c;
        if (r0 < n) *(float2*)(Co + (size_t)r0 * 64 + ch) = make_float2(acc[nt][0], acc[nt][1]);
        if (r1 < n) *(float2*)(Co + (size_t)r1 * 64 + ch) = make_float2(acc[nt][2], acc[nt][3]);
        float s0 = acc[nt][0] + acc[nt][2];
        float s1 = acc[nt][1] + acc[nt][3];
        float q0 = acc[nt][0] * acc[nt][0] + acc[nt][2] * acc[nt][2];
        float q1 = acc[nt][1] * acc[nt][1] + acc[nt][3] * acc[nt][3];
#pragma unroll
        for (int d = 4; d < 32; d <<= 1) {
            s0 += __shfl_xor_sync(0xffffffffu, s0, d);
            s1 += __shfl_xor_sync(0xffffffffu, s1, d);
            q0 += __shfl_xor_sync(0xffffffffu, q0, d);
            q1 += __shfl_xor_sync(0xffffffffu, q1, d);
        }
        if (lane < 4) {
            atomicAdd(&csum[ch], s0);
            atomicAdd(&csum[ch + 1], s1);
            atomicAdd(&csq[ch], q0);
            atomicAdd(&csq[ch + 1], q1);
        }
    }
    __syncthreads();
    if (tid < 64)       atomicAdd(&statsg[tid], csum[tid]);
    else if (tid < 128) atomicAdd(&statsg[tid], csq[tid - 64]);
}

__device__ __forceinline__ void load_coef(float* sc, const float* __restrict__ stats,
                                          const float* __restrict__ g,
                                          const float* __restrict__ b, int n, int tid) {
    if (tid < 64) {
        float inv_n = 1.f / (float)n;
        float mean = stats[tid] * inv_n;
        float var = stats[64 + tid] * inv_n - mean * mean;
        float a = g[tid] * rsqrtf(var + 1e-3f);
        sc[tid] = a;
        sc[64 + tid] = b[tid] - mean * a;
    }
}

// ---------------- prepack ----------------
__global__ void k_prepack(const float* __restrict__ Wlw, const float* __restrict__ Ww,
                          const float* __restrict__ Wproj, const float* __restrict__ Wfuse,
                          const float* __restrict__ Wc1, const float* __restrict__ Wc2,
                          unsigned* __restrict__ pack) {
    int t = blockIdx.x;
    const float* src;
    if (t < 3)       src = Wlw  + t * 4096;
    else if (t < 6)  src = Ww   + (t - 3) * 4096;
    else if (t < 10) src = Wproj+ (t - 6) * 4096;
    else if (t < 12) src = Wfuse+ (t - 10) * 4096;
    else if (t < 39) src = Wc1  + (t - 12) * 4096;
    else             src = Wc2  + (t - 39) * 4096;
    unsigned* ph = pack + (size_t)t * 4608;
    unsigned* pl = ph + 2304;
    for (int idx = threadIdx.x; idx < 2048; idx += 256) {
        int cout = idx & 63, p = idx >> 6;
        unsigned h, l;
        split2(src[2 * p * 64 + cout], src[(2 * p + 1) * 64 + cout], h, l);
        ph[cout * AS + p] = h;
        pl[cout * AS + p] = l;
    }
}

// F = relu(bn(rawF)) + feat; emit bf16 planes of F
__global__ void k_bnrelu_add_split(float* __restrict__ F, const float* __restrict__ stats,
                                   const float* __restrict__ g, const float* __restrict__ b,
                                   const float* __restrict__ feat,
                                   __nv_bfloat162* __restrict__ H,
                                   __nv_bfloat162* __restrict__ L, int n, int total4) {
    __shared__ float sc[128];
    load_coef(sc, stats, g, b, n, threadIdx.x);
    __syncthreads();
    int i = blockIdx.x * 256 + threadIdx.x;
    if (i >= total4) return;
    int ch = (i & 15) * 4;
    float4 x = ((const float4*)F)[i];
    float4 r = ((const float4*)feat)[i];
    x.x = fmaxf(x.x * sc[ch + 0] + sc[64 + ch + 0], 0.f) + r.x;
    x.y = fmaxf(x.y * sc[ch + 1] + sc[64 + ch + 1], 0.f) + r.y;
    x.z = fmaxf(x.z * sc[ch + 2] + sc[64 + ch + 2], 0.f) + r.z;
    x.w = fmaxf(x.w * sc[ch + 3] + sc[64 + ch + 3], 0.f) + r.w;
    ((float4*)F)[i] = x;
    unsigned h0, l0, h1, l1;
    split2(x.x, x.y, h0, l0);
    split2(x.z, x.w, h1, l1);
    ((uint2*)H)[i] = make_uint2(h0, h1);
    ((uint2*)L)[i] = make_uint2(l0, l1);
}

__global__ void k_bnrelu_split(const float* __restrict__ P, const float* __restrict__ stats,
                               const float* __restrict__ g, const float* __restrict__ b,
                               __nv_bfloat162* __restrict__ H,
                               __nv_bfloat162* __restrict__ L, int n, int total4) {
    __shared__ float sc[128];
    load_coef(sc, stats, g, b, n, threadIdx.x);
    __syncthreads();
    int i = blockIdx.x * 256 + threadIdx.x;
    if (i >= total4) return;
    int ch = (i & 15) * 4;
    float4 x = ((const float4*)P)[i];
    x.x = fmaxf(x.x * sc[ch + 0] + sc[64 + ch + 0], 0.f);
    x.y = fmaxf(x.y * sc[ch + 1] + sc[64 + ch + 1], 0.f);
    x.z = fmaxf(x.z * sc[ch + 2] + sc[64 + ch + 2], 0.f);
    x.w = fmaxf(x.w * sc[ch + 3] + sc[64 + ch + 3], 0.f);
    unsigned h0, l0, h1, l1;
    split2(x.x, x.y, h0, l0);
    split2(x.z, x.w, h1, l1);
    ((uint2*)H)[i] = make_uint2(h0, h1);
    ((uint2*)L)[i] = make_uint2(l0, l1);
}

// ---------------- tensor-core kernels ----------------
// 7 GEMMs sharing A=feat (converted in staging): outputs P0..P2,Q0..Q3 + stats
__global__ __launch_bounds__(NTHR)
void k_mma_gemm7(const float* __restrict__ feat, const unsigned* __restrict__ pack,
                 float* __restrict__ bufs, float* __restrict__ statsg, int n) {
    extern __shared__ unsigned sm[];     // A:[0,9216) B0:[9216,13824) B1:[13824,18432)
    __shared__ float csum[64], csq[64];
    const int tidx[7] = {0, 1, 2, 6, 7, 8, 9};
    int tid = threadIdx.x, wid = tid >> 5, lane = tid & 31;
    int row0 = blockIdx.x * TM;
    stage_B(sm + OFF_B, pack + (size_t)tidx[0] * 4608, tid);
    cp_commit();
#pragma unroll
    for (int i = 0; i < 8; ++i) {   // convert feat -> hi/lo planes
        int idx = tid + i * NTHR;
        int r = idx >> 4, c4 = idx & 15;
        int grow = row0 + r;
        float4 v = make_float4(0.f, 0.f, 0.f, 0.f);
        if (grow < n) v = *(const float4*)(feat + (size_t)grow * 64 + c4 * 4);
        a_store(sm, r, c4, v);
    }
    for (int t = 0; t < 7; ++t) {
        unsigned* bcur = sm + OFF_B + (t & 1) * 4608;
        if (t + 1 < 7) {
            stage_B(sm + OFF_B + ((t + 1) & 1) * 4608, pack + (size_t)tidx[t + 1] * 4608, tid);
            cp_commit();
            cp_wait<1>();
        } else {
            cp_wait<0>();
        }
        if (tid < 64) { csum[tid] = 0.f; csq[tid] = 0.f; }
        __syncthreads();
        float acc[8][4] = {};
        mma_compute(sm, bcur, acc, wid, lane);
        epilogue_stats(acc, bufs + (size_t)t * ROWSZ, statsg + t * 128,
                       csum, csq, row0, n, wid, lane, tid);
        __syncthreads();
    }
}

// gather conv, double-buffered over 27 taps; + stats
__global__ __launch_bounds__(NTHR)
void k_mma_conv(const uint4* __restrict__ AH, const uint4* __restrict__ AL,
                const int* __restrict__ nbr, const unsigned* __restrict__ pack,
                float* __restrict__ Co, float* __restrict__ statsg, int n) {
    extern __shared__ unsigned sm[];
    __shared__ float csum[64], csq[64];
    int tid = threadIdx.x, wid = tid >> 5, lane = tid & 31;
    int row0 = blockIdx.x * TM;
    int row = tid >> 1, pl = tid & 1;
    int gr = row0 + row;
    bool v = gr < n;
    const uint4* base = pl ? AL : AH;
    if (tid < 64) { csum[tid] = 0.f; csq[tid] = 0.f; }
    {
        unsigned* b0 = sm;
        stage_B(b0 + OFF_B, pack, tid);
        int sr = v ? __ldg(&nbr[(size_t)gr * 27]) : 0;
        const uint4* s = base + (size_t)sr * 8;
        unsigned* d = b0 + (pl ? OFF_AL : 0) + row * AS;
#pragma unroll
        for (int c = 0; c < 8; ++c) cp16(d + c * 4, s + c, v);
        cp_commit();
    }
    float acc[8][4] = {};
    for (int k = 0; k < 27; ++k) {
        unsigned* cur = sm + (k & 1) * BUFU;
        if (k + 1 < 27) {
            unsigned* nb = sm + ((k + 1) & 1) * BUFU;
            stage_B(nb + OFF_B, pack + (size_t)(k + 1) * 4608, tid);
            int sr = v ? __ldg(&nbr[(size_t)gr * 27 + k + 1]) : 0;
            const uint4* s = base + (size_t)sr * 8;
            unsigned* d = nb + (pl ? OFF_AL : 0) + row * AS;
#pragma unroll
            for (int c = 0; c < 8; ++c) cp16(d + c * 4, s + c, v);
            cp_commit();
            cp_wait<1>();
        } else {
            cp_wait<0>();
        }
        __syncthreads();
        mma_compute(cur, cur + OFF_B, acc, wid, lane);
        __syncthreads();
    }
    epilogue_stats(acc, Co, statsg, csum, csq, row0, n, wid, lane, tid);
}

// per-scale (gridDim.y=3): P = exp((relu(bn(P)) - mean[cl]) @ W_w); den += P
__global__ __launch_bounds__(NTHR)
void k_mma_submean_exp(float* __restrict__ bufs, const float* __restrict__ statsb,
                       const float* __restrict__ glw, const float* __restrict__ blw,
                       const unsigned* __restrict__ pack, const float* __restrict__ mean,
                       const float* __restrict__ cnt,
                       const int* __restrict__ cl0, const int* __restrict__ cl1,
                       const int* __restrict__ cl2, float* __restrict__ den, int n) {
    extern __shared__ unsigned buf[];
    __shared__ float coef[128];
    __shared__ int   cls[TM];
    __shared__ float cinv[TM];
    int s = blockIdx.y;
    const int* cl = (s == 0) ? cl0 : ((s == 1) ? cl1 : cl2);
    int soff = c_soff[s];
    float* P = bufs + (size_t)s * ROWSZ;
    int tid = threadIdx.x, wid = tid >> 5, lane = tid & 31;
    int row0 = blockIdx.x * TM;
    load_coef(coef, statsb + s * 128, glw + s * 64, blw + s * 64, n, tid);
    if (tid < 128) {
        int r = row0 + tid;
        int c = (r < n) ? cl[r] : 0;
        cls[tid] = c;
        cinv[tid] = 1.f / fmaxf(cnt[soff + c], 1.f);
    }
    stage_B(buf + OFF_B, pack + (size_t)(3 + s) * 4608, tid);
    cp_commit();
    __syncthreads();
#pragma unroll
    for (int i = 0; i < 8; ++i) {
        int idx = tid + i * NTHR;
        int r = idx >> 4, c4 = idx & 15;
        int grow = row0 + r;
        float4 vv = make_float4(0.f, 0.f, 0.f, 0.f);
        if (grow < n) {
            vv = *(const float4*)(P + (size_t)grow * 64 + c4 * 4);
            float4 ms = *(const float4*)(mean + (size_t)(soff + cls[r]) * 64 + c4 * 4);
            float ci = cinv[r];
            int ch = c4 * 4;
            vv.x = fmaxf(vv.x * coef[ch + 0] + coef[64 + ch + 0], 0.f) - ms.x * ci;
            vv.y = fmaxf(vv.y * coef[ch + 1] + coef[64 + ch + 1], 0.f) - ms.y * ci;
            vv.z = fmaxf(vv.z * coef[ch + 2] + coef[64 + ch + 2], 0.f) - ms.z * ci;
            vv.w = fmaxf(vv.w * coef[ch + 3] + coef[64 + ch + 3], 0.f) - ms.w * ci;
        }
        a_store(buf, r, c4, vv);
    }
    cp_wait<0>();
    __syncthreads();
    float acc[8][4] = {};
    mma_compute(buf, buf + OFF_B, acc, wid, lane);
    int g = lane >> 2, c = lane & 3;
    int lr0 = wid * 16 + g, lr1 = lr0 + 8;
    int r0 = row0 + lr0, r1 = row0 + lr1;
    float* d0 = den + (size_t)(soff + cls[lr0]) * 64;
    float* d1 = den + (size_t)(soff + cls[lr1]) * 64;
#pragma unroll
    for (int nt = 0; nt < 8; ++nt) {
        int ch = nt * 8 + 2 * c;
        if (r0 < n) {
            float e0 = __expf(acc[nt][0]), e1 = __expf(acc[nt][1]);
            *(float2*)(P + (size_t)r0 * 64 + ch) = make_float2(e0, e1);
            red_add_v2(d0 + ch, e0, e1);
        }
        if (r1 < n) {
            float e2 = __expf(acc[nt][2]), e3 = __expf(acc[nt][3]);
            *(float2*)(P + (size_t)r1 * 64 + ch) = make_float2(e2, e3);
            red_add_v2(d1 + ch, e2, e3);
        }
    }
}

// fuse GEMM: Co = relu(bn(Q))@Wf[0:64] + mix@Wf[64:128] + stats
__global__ __launch_bounds__(NTHR)
void k_mma_gemm2(const float* __restrict__ Q, const float* __restrict__ stats,
                 const float* __restrict__ gg, const float* __restrict__ bb,
                 const unsigned* __restrict__ tiles, const float* __restrict__ segS,
                 const int* __restrict__ cl0, const int* __restrict__ cl1,
                 const int* __restrict__ cl2, const float* __restrict__ adp,
                 float* __restrict__ Co, float* __restrict__ statsg, int n) {
    extern __shared__ unsigned buf[];
    __shared__ float csum[64], csq[64];
    __shared__ float coef[128];
    __shared__ int   cls[3][TM];
    __shared__ float sad[3][TM];
    int tid = threadIdx.x, wid = tid >> 5, lane = tid & 31;
    int row0 = blockIdx.x * TM;
    if (tid < 64) { csum[tid] = 0.f; csq[tid] = 0.f; }
    load_coef(coef, stats, gg, bb, n, tid);
    if (tid < 128) {
        int r = row0 + tid;
        bool v = r < n;
        cls[0][tid] = v ? cl0[r] : 0;
        cls[1][tid] = v ? cl1[r] : 0;
        cls[2][tid] = v ? cl2[r] : 0;
        sad[0][tid] = v ? adp[(size_t)r * 3 + 0] : 0.f;
        sad[1][tid] = v ? adp[(size_t)r * 3 + 1] : 0.f;
        sad[2][tid] = v ? adp[(size_t)r * 3 + 2] : 0.f;
    }
    __syncthreads();
    float acc[8][4] = {};
#pragma unroll
    for (int p = 0; p < 2; ++p) {
        stage_B(buf + OFF_B, tiles + (size_t)p * 4608, tid);
        cp_commit();
#pragma unroll
        for (int i = 0; i < 8; ++i) {
            int idx = tid + i * NTHR;
            int r = idx >> 4, c4 = idx & 15;
            int grow = row0 + r;
            float4 vv = make_float4(0.f, 0.f, 0.f, 0.f);
            if (grow < n) {
                if (p == 0) {
                    vv = *(const float4*)(Q + (size_t)grow * 64 + c4 * 4);
                    int ch = c4 * 4;
                    vv.x = fmaxf(vv.x * coef[ch + 0] + coef[64 + ch + 0], 0.f);
                    vv.y = fmaxf(vv.y * coef[ch + 1] + coef[64 + ch + 1], 0.f);
                    vv.z = fmaxf(vv.z * coef[ch + 2] + coef[64 + ch + 2], 0.f);
                    vv.w = fmaxf(vv.w * coef[ch + 3] + coef[64 + ch + 3], 0.f);
                } else {
                    float w0 = sad[0][r], w1 = sad[1][r], w2 = sad[2][r];
                    float4 a = *(const float4*)(segS + (size_t)(0 + cls[0][r]) * 64 + c4 * 4);
                    float4 bv = *(const float4*)(segS + (size_t)(4096 + cls[1][r]) * 64 + c4 * 4);
                    float4 cc = *(const float4*)(segS + (size_t)(36864 + cls[2][r]) * 64 + c4 * 4);
                    vv.x = w0 * a.x + w1 * bv.x + w2 * cc.x;
                    vv.y = w0 * a.y + w1 * bv.y + w2 * cc.y;
                    vv.z = w0 * a.z + w1 * bv.z + w2 * cc.z;
                    vv.w = w0 * a.w + w1 * bv.w + w2 * cc.w;
                }
            }
            a_store(buf, r, c4, vv);
        }
        cp_wait<0>();
        __syncthreads();
        mma_compute(buf, buf + OFF_B, acc, wid, lane);
        __syncthreads();
    }
    epilogue_stats(acc, Co, statsg, csum, csq, row0, n, wid, lane, tid);
}

// ---------------- small / elementwise kernels ----------------
__global__ void k_adp(const float* __restrict__ feat, const float* __restrict__ Wa,
                      float* __restrict__ adp, int n) {
    __shared__ float w[192];
    if (threadIdx.x < 192) w[threadIdx.x] = Wa[threadIdx.x];
    __syncthreads();
    int row = blockIdx.x * blockDim.x + threadIdx.x;
    if (row >= n) return;
    float s0 = 0.f, s1 = 0.f, s2 = 0.f;
    const float* f = feat + (size_t)row * 64;
#pragma unroll 16
    for (int c = 0; c < 64; ++c) {
        float v = f[c];
        s0 += v * w[c * 3 + 0];
        s1 += v * w[c * 3 + 1];
        s2 += v * w[c * 3 + 2];
    }
    float m = fmaxf(s0, fmaxf(s1, s2));
    float e0 = __expf(s0 - m), e1 = __expf(s1 - m), e2 = __expf(s2 - m);
    float inv = 1.f / (e0 + e1 + e2);
    adp[(size_t)row * 3 + 0] = e0 * inv;
    adp[(size_t)row * 3 + 1] = e1 * inv;
    adp[(size_t)row * 3 + 2] = e2 * inv;
}

// per-scale (gridDim.y=3): mean-arena += relu(bn(P)), cnt++
__global__ void k_segsum3(const float* __restrict__ bufs, const float* __restrict__ statsb,
                          const float* __restrict__ glw, const float* __restrict__ blw,
                          const int* __restrict__ cl0, const int* __restrict__ cl1,
                          const int* __restrict__ cl2, float* __restrict__ mean,
                          float* __restrict__ cnt, int n) {
    __shared__ float sc[128];
    int s = blockIdx.y;
    load_coef(sc, statsb + s * 128, glw + s * 64, blw + s * 64, n, threadIdx.x);
    __syncthreads();
    int row = blockIdx.x * blockDim.x + threadIdx.x;
    if (row >= n) return;
    const int* cl = (s == 0) ? cl0 : ((s == 1) ? cl1 : cl2);
    int c = c_soff[s] + cl[row];
    const float* p = bufs + (size_t)s * ROWSZ + (size_t)row * 64;
    float* sg = mean + (size_t)c * 64;
#pragma unroll
    for (int c4 = 0; c4 < 16; ++c4) {
        float4 x = *(const float4*)(p + c4 * 4);
        x.x = fmaxf(x.x * sc[c4 * 4 + 0] + sc[64 + c4 * 4 + 0], 0.f);
        x.y = fmaxf(x.y * sc[c4 * 4 + 1] + sc[64 + c4 * 4 + 1], 0.f);
        x.z = fmaxf(x.z * sc[c4 * 4 + 2] + sc[64 + c4 * 4 + 2], 0.f);
        x.w = fmaxf(x.w * sc[c4 * 4 + 3] + sc[64 + c4 * 4 + 3], 0.f);
        red_add_v4(sg + c4 * 4, x);
    }
    atomicAdd(&cnt[c], 1.f);
}

// per-scale (gridDim.y=3): segS += relu(bn(Q)) * expP / (den[cl]+1e-6)
__global__ void k_pw3(const float* __restrict__ bufs, const float* __restrict__ statsb,
                      const float* __restrict__ gproj, const float* __restrict__ bproj,
                      const float* __restrict__ den,
                      const int* __restrict__ cl0, const int* __restrict__ cl1,
                      const int* __restrict__ cl2, float* __restrict__ segS, int n) {
    __shared__ float sc[128];
    int s = blockIdx.y;
    load_coef(sc, statsb + (3 + s) * 128, gproj + s * 64, bproj + s * 64, n, threadIdx.x);
    __syncthreads();
    int row = blockIdx.x * blockDim.x + threadIdx.x;
    if (row >= n) return;
    const int* cl = (s == 0) ? cl0 : ((s == 1) ? cl1 : cl2);
    int c = c_soff[s] + cl[row];
    const float* q = bufs + (size_t)(3 + s) * ROWSZ + (size_t)row * 64;
    const float* p = bufs + (size_t)s * ROWSZ + (size_t)row * 64;
    const float* d = den + (size_t)c * 64;
    float* sg = segS + (size_t)c * 64;
#pragma unroll
    for (int c4 = 0; c4 < 16; ++c4) {
        float4 qv = *(const float4*)(q + c4 * 4);
        float4 pv = *(const float4*)(p + c4 * 4);
        float4 dv = *(const float4*)(d + c4 * 4);
        float4 o;
        o.x = fmaxf(qv.x * sc[c4 * 4 + 0] + sc[64 + c4 * 4 + 0], 0.f) * pv.x / (dv.x + 1e-6f);
        o.y = fmaxf(qv.y * sc[c4 * 4 + 1] + sc[64 + c4 * 4 + 1], 0.f) * pv.y / (dv.y + 1e-6f);
        o.z = fmaxf(qv.z * sc[c4 * 4 + 2] + sc[64 + c4 * 4 + 2], 0.f) * pv.z / (dv.z + 1e-6f);
        o.w = fmaxf(qv.w * sc[c4 * 4 + 3] + sc[64 + c4 * 4 + 3], 0.f) * pv.w / (dv.w + 1e-6f);
        red_add_v4(sg + c4 * 4, o);
    }
}

// out = relu(bn(H) + F)
__global__ void k_final(const float* __restrict__ H, const float* __restrict__ stats,
                        const float* __restrict__ g, const float* __restrict__ b,
                        const float* __restrict__ F, float* __restrict__ out,
                        int n, int total4) {
    __shared__ float sc[128];
    load_coef(sc, stats, g, b, n, threadIdx.x);
    __syncthreads();
    int i = blockIdx.x * 256 + threadIdx.x;
    if (i >= total4) return;
    int ch = (i & 15) * 4;
    float4 x = ((const float4*)H)[i];
    float4 r = ((const float4*)F)[i];
    x.x = fmaxf(x.x * sc[ch + 0] + sc[64 + ch + 0] + r.x, 0.f);
    x.y = fmaxf(x.y * sc[ch + 1] + sc[64 + ch + 1] + r.y, 0.f);
    x.z = fmaxf(x.z * sc[ch + 2] + sc[64 + ch + 2] + r.z, 0.f);
    x.w = fmaxf(x.w * sc[ch + 3] + sc[64 + ch + 3] + r.w, 0.f);
    ((float4*)out)[i] = x;
}

// ---------------------------------------------------------------------------
extern "C" void kernel_launch(void* const* d_in, const int* in_sizes, int n_in,
                              void* d_out, int out_size) {
    const float* feat   = (const float*)d_in[0];
    const int*   cl0    = (const int*)d_in[1];
    const int*   cl1    = (const int*)d_in[2];
    const int*   cl2    = (const int*)d_in[3];
    const int*   nbr    = (const int*)d_in[4];
    const float* W_lw   = (const float*)d_in[5];
    const float* g_lw   = (const float*)d_in[6];
    const float* b_lw   = (const float*)d_in[7];
    const float* W_w    = (const float*)d_in[8];
    const float* W_proj = (const float*)d_in[9];
    const float* g_proj = (const float*)d_in[10];
    const float* b_proj = (const float*)d_in[11];
    const float* W_adp  = (const float*)d_in[12];
    const float* W_fuse = (const float*)d_in[13];
    const float* g_fuse = (const float*)d_in[14];
    const float* b_fuse = (const float*)d_in[15];
    const float* W_c1   = (const float*)d_in[16];
    const float* g_c1   = (const float*)d_in[17];
    const float* b_c1   = (const float*)d_in[18];
    const float* W_c2   = (const float*)d_in[19];
    const float* g_c2   = (const float*)d_in[20];
    const float* b_c2   = (const float*)d_in[21];
    float* out = (float*)d_out;
    int n = in_sizes[1];

    float *pBufs, *pF, *pMean, *pDen, *pSegS, *pCnt, *pStats, *pAdp;
    __nv_bfloat162 *pH, *pL;
    unsigned *pPack;
    cudaGetSymbolAddress((void**)&pBufs, g_bufs);
    cudaGetSymbolAddress((void**)&pF, g_bufF);
    cudaGetSymbolAddress((void**)&pH, g_pH);
    cudaGetSymbolAddress((void**)&pL, g_pL);
    cudaGetSymbolAddress((void**)&pMean, g_segMean);
    cudaGetSymbolAddress((void**)&pDen, g_segDen);
    cudaGetSymbolAddress((void**)&pSegS, g_segS);
    cudaGetSymbolAddress((void**)&pCnt, g_cnt);
    cudaGetSymbolAddress((void**)&pStats, g_statsA);
    cudaGetSymbolAddress((void**)&pAdp, g_adpv);
    cudaGetSymbolAddress((void**)&pPack, g_wpack);

    const int GB = (n + TM - 1) / TM;
    const int EB = (n + 255) / 256;
    const int total4 = n * 16;
    const int SB = (total4 + 255) / 256;
    const int SM_G7 = 18432 * 4;        // 73728B
    const int SM_1  = BUFU * 4;         // 55296B
    const int SM_CV = BUFU * 8;         // 110592B

    cudaFuncSetAttribute(k_mma_gemm7, cudaFuncAttributeMaxDynamicSharedMemorySize, SM_G7);
    cudaFuncSetAttribute(k_mma_submean_exp, cudaFuncAttributeMaxDynamicSharedMemorySize, SM_1);
    cudaFuncSetAttribute(k_mma_gemm2, cudaFuncAttributeMaxDynamicSharedMemorySize, SM_1);
    cudaFuncSetAttribute(k_mma_conv, cudaFuncAttributeMaxDynamicSharedMemorySize, SM_CV);

    const uint4* AH = (const uint4*)pH;
    const uint4* AL = (const uint4*)pL;
    float* Qb3 = pBufs + 6 * ROWSZ;

    k_prepack<<<66, 256>>>(W_lw, W_w, W_proj, W_fuse, W_c1, W_c2, pPack);
    k_adp<<<EB, 256>>>(feat, W_adp, pAdp, n);

    // 7 feat-GEMMs (feat converted in staging)
    cudaMemsetAsync(pStats, 0, 7 * 128 * sizeof(float));
    k_mma_gemm7<<<GB, NTHR, SM_G7>>>(feat, pPack, pBufs, pStats, n);

    // cluster attention, all 3 scales batched
    cudaMemsetAsync(pMean, 0, (size_t)SEGTOT * 64 * sizeof(float));
    cudaMemsetAsync(pCnt, 0, (size_t)SEGTOT * sizeof(float));
    k_segsum3<<<dim3(EB, 3), 256>>>(pBufs, pStats, g_lw, b_lw, cl0, cl1, cl2,
                                    pMean, pCnt, n);
    cudaMemsetAsync(pDen, 0, (size_t)SEGTOT * 64 * sizeof(float));
    k_mma_submean_exp<<<dim3(GB, 3), NTHR, SM_1>>>(pBufs, pStats, g_lw, b_lw, pPack,
                                                   pMean, pCnt, cl0, cl1, cl2, pDen, n);
    cudaMemsetAsync(pSegS, 0, (size_t)SEGTOT * 64 * sizeof(float));
    k_pw3<<<dim3(EB, 3), 256>>>(pBufs, pStats, g_proj, b_proj, pDen,
                                cl0, cl1, cl2, pSegS, n);

    // fused = relu(bn([relu(bn(Q3)), mix] @ W_fuse)) + feat
    cudaMemsetAsync(pStats + 7 * 128, 0, 128 * sizeof(float));
    k_mma_gemm2<<<GB, NTHR, SM_1>>>(Qb3, pStats + 6 * 128, g_proj + 192, b_proj + 192,
                                    pPack + (size_t)10 * 4608, pSegS,
                                    cl0, cl1, cl2, pAdp, pF, pStats + 7 * 128, n);
    k_bnrelu_add_split<<<SB, 256>>>(pF, pStats + 7 * 128, g_fuse, b_fuse, feat,
                                    pH, pL, n, total4);
    // conv1 -> split ; conv2 -> final
    cudaMemsetAsync(pStats + 8 * 128, 0, 128 * sizeof(float));
    k_mma_conv<<<GB, NTHR, SM_CV>>>(AH, AL, nbr, pPack + (size_t)12 * 4608,
                                    pBufs, pStats + 8 * 128, n);
    k_bnrelu_split<<<SB, 256>>>(pBufs, pStats + 8 * 128, g_c1, b_c1, pH, pL, n, total4);
    cudaMemsetAsync(pStats + 9 * 128, 0, 128 * sizeof(float));
    k_mma_conv<<<GB, NTHR, SM_CV>>>(AH, AL, nbr, pPack + (size_t)39 * 4608,
                                    pBufs + ROWSZ, pStats + 9 * 128, n);
    k_final<<<SB, 256>>>(pBufs + ROWSZ, pStats + 9 * 128, g_c2, b_c2, pF, out, n, total4);
}